// round 11
// baseline (speedup 1.0000x reference)
#include <cuda_runtime.h>
#include <cuda_bf16.h>
#include <math.h>

#define HWp 16384
#define Hdim 128
#define Wdim 128
#define Bn 8
#define Tn 10
#define Dn 10

// ---------------- scratch state (device globals) ----------------
__device__ float g_xx[(size_t)Bn*Tn*Dn*HWp];
__device__ float g_hs0[(size_t)Bn*Tn*HWp];
__device__ float g_cs0[(size_t)Bn*Tn*HWp];
__device__ float g_hs1[(size_t)Bn*Tn*64*HWp];
__device__ float g_cs1[(size_t)Bn*Tn*64*HWp];
__device__ float g_score[(size_t)Bn*Tn*HWp];
__device__ float g_hid[(size_t)Tn*Bn*32*HWp];
__device__ float g_z[(size_t)Bn*256*HWp];
__device__ float g_hatt[(size_t)Bn*64*HWp];
__device__ float g_tc[(size_t)Tn*Bn*32*HWp];

// pre-packed fragment-order bf16x2 weights (hi/lo)
#define WTOT 211968
__device__ unsigned g_whi[WTOT];
__device__ unsigned g_wlo[WTOT];
// offsets (words): layout [(cb*9+tap)*MTall + mtile]*128 + lane*4 + j
#define OFF_ENC1  0
#define SZ_ENC1   92160      // nCh=5, MTall=16
#define OFF_DEC0  92160
#define SZ_DEC0   92160
#define OFF_WA1   184320
#define SZ_WA1    2304       // nCh=1, MTall=2
#define OFF_WT1HC 186624
#define SZ_WT1HC  18432      // nCh=8, MTall=2
#define OFF_ENC0  205056
#define SZ_ENC0   1152       // nCh=1, MTall=1
#define OFF_DEC1  206208
#define SZ_DEC1   5760       // nCh=5, MTall=1

__device__ __forceinline__ float sigm(float x) { return 1.f / (1.f + __expf(-x)); }

__device__ __forceinline__ unsigned packbf(__nv_bfloat16 lo16, __nv_bfloat16 hi16) {
    return ((unsigned)__bfloat16_as_ushort(hi16) << 16) | __bfloat16_as_ushort(lo16);
}
__device__ __forceinline__ void splitbf(float v, __nv_bfloat16& h, __nv_bfloat16& l) {
    h = __float2bfloat16(v);
    l = __float2bfloat16(v - __bfloat162float(h));
}
__device__ __forceinline__ void mma16(float* c, const unsigned* a, const unsigned* b) {
    asm volatile("mma.sync.aligned.m16n8k16.row.col.f32.bf16.bf16.f32 "
        "{%0,%1,%2,%3}, {%4,%5,%6,%7}, {%8,%9}, {%0,%1,%2,%3};"
        : "+f"(c[0]), "+f"(c[1]), "+f"(c[2]), "+f"(c[3])
        : "r"(a[0]), "r"(a[1]), "r"(a[2]), "r"(a[3]), "r"(b[0]), "r"(b[1]));
}

// ---------------- weight pre-pack into m16n8k16 fragment order ----------------
// a0:(row g, k=2q,2q+1) a1:(row g+8, k=2q,2q+1) a2:(row g, k=2q+8,2q+9) a3:(row g+8, k=2q+8,2q+9)
__global__ void wprep(const float* __restrict__ wgt, int Cw, int Cin, int Cout,
                      int MTall, int nCh, unsigned* __restrict__ whi,
                      unsigned* __restrict__ wlo)
{
    int idx = blockIdx.x * blockDim.x + threadIdx.x;
    int total = nCh * 9 * MTall * 128;
    if (idx >= total) return;
    int li = idx & 127;
    int j = li & 3, ln = li >> 2;
    int f = idx >> 7;
    int mtile = f % MTall;
    int tap = (f / MTall) % 9;
    int cb = f / (MTall * 9);
    int g = ln >> 2, q = ln & 3;
    int co = mtile * 16 + g + (j & 1) * 8;
    int kb = 2 * q + (j >> 1) * 8;
    int ci0 = cb * 16 + kb;
    float w0 = 0.f, w1 = 0.f;
    if (co < Cout) {
        if (ci0 < Cin)     w0 = wgt[((long)co * Cw + ci0) * 9 + tap];
        if (ci0 + 1 < Cin) w1 = wgt[((long)co * Cw + ci0 + 1) * 9 + tap];
    }
    __nv_bfloat16 h0, l0, h1, l1;
    splitbf(w0, h0, l0);
    splitbf(w1, h1, l1);
    whi[idx] = packbf(h0, h1);
    wlo[idx] = packbf(l0, l1);
}

// =============== implicit-GEMM 3x3 conv, bf16 hi/lo split, m16n8k16 ===============
// Block: 256 thr (8 warps), MBLK out channels x 256 px (16x16 tile).
// Cin chunks of 16 channels (8 packed ci-pair planes). Stage-ahead double buffer,
// one __syncthreads per chunk. Weights as LDG.128 from fragment-packed global.
template <int MBLK, int WN>
__global__ void __launch_bounds__(256) mmaconv(
    const float* __restrict__ in0, int n0, long c0s, long b0s, long r0s,
    const float* __restrict__ in1, int n1, long c1s, long b1s, long r1s,
    const float* __restrict__ in2, int n2, long c2s, long b2s, long r2s,
    const unsigned* __restrict__ whi, const unsigned* __restrict__ wlo, int MTall,
    const float* __restrict__ bias, int act,
    float* __restrict__ out, long o_rs, long obs, int Cin, int Cout)
{
    constexpr int WM = 8 / WN;
    constexpr int MT = MBLK / (16 * WM);
    constexpr int NT = 32 / WN;

    __shared__ unsigned in_hi[2][8 * 360];   // packed bf16x2 (ci, ci+1) per px
    __shared__ unsigned in_lo[2][8 * 360];

    int b = blockIdx.z % Bn;
    int r = blockIdx.z / Bn;
    int cobase = blockIdx.y * MBLK;
    int ty0 = (blockIdx.x >> 3) * 16, tx0 = (blockIdx.x & 7) * 16;

    int tid = threadIdx.x;
    int wid = tid >> 5, lane = tid & 31;
    int g = lane >> 2, q = lane & 3;
    int cowb = (wid / WN) * (MT * 16);
    int pwb  = (wid % WN) * (NT * 8);

    int pixoff[NT];
#pragma unroll
    for (int nt = 0; nt < NT; nt++) {
        int px = pwb + nt * 8 + g;
        pixoff[nt] = (px >> 4) * 19 + (px & 15);
    }

    float acc[MT][NT][4];
#pragma unroll
    for (int mt = 0; mt < MT; mt++)
#pragma unroll
        for (int nt = 0; nt < NT; nt++)
#pragma unroll
            for (int i = 0; i < 4; i++) acc[mt][nt][i] = 0.f;

    auto ldci = [&](int cig, int go) -> float {
        if (cig >= Cin) return 0.f;
        const float* src;
        if (cig < n0)           src = in0 + (long)b * b0s + (long)r * r0s + (long)cig * c0s;
        else if (cig < n0 + n1) src = in1 + (long)b * b1s + (long)r * r1s + (long)(cig - n0) * c1s;
        else                    src = in2 + (long)b * b2s + (long)r * r2s + (long)(cig - n0 - n1) * c2s;
        return src[go];
    };
    auto stage = [&](int cb, int buf) {
#pragma unroll
        for (int jj = 0; jj < 11; jj++) {
            int i = tid + jj * 256;
            if (i >= 2592) continue;
            int cp = i / 324; int rem = i - cp * 324;
            int rr = rem / 18, cc = rem - rr * 18;
            int gy = ty0 + rr - 1, gx = tx0 + cc - 1;
            float v0 = 0.f, v1 = 0.f;
            if (gy >= 0 && gy < Hdim && gx >= 0 && gx < Wdim) {
                int go = gy * Wdim + gx;
                int ci0 = cb * 16 + 2 * cp;
                v0 = ldci(ci0, go);
                v1 = ldci(ci0 + 1, go);
            }
            __nv_bfloat16 h0, l0, h1, l1;
            splitbf(v0, h0, l0);
            splitbf(v1, h1, l1);
            int so = cp * 360 + rr * 19 + cc;
            in_hi[buf][so] = packbf(h0, h1);
            in_lo[buf][so] = packbf(l0, l1);
        }
    };

    int nCh = (Cin + 15) >> 4;
    stage(0, 0);
    __syncthreads();

    for (int cb = 0; cb < nCh; cb++) {
        int buf = cb & 1;
        if (cb + 1 < nCh) stage(cb + 1, buf ^ 1);

        long wchunk = (long)cb * 9 * MTall * 128;
#pragma unroll
        for (int tap = 0; tap < 9; tap++) {
            int toff = (tap / 3) * 19 + (tap % 3);
            uint4 ahi[MT], alo[MT];
#pragma unroll
            for (int mt = 0; mt < MT; mt++) {
                int mtg = (cobase >> 4) + (cowb >> 4) + mt;
                long fb = wchunk + ((long)tap * MTall + mtg) * 128 + lane * 4;
                ahi[mt] = *(const uint4*)&whi[fb];
                alo[mt] = *(const uint4*)&wlo[fb];
            }
            const unsigned* bh0 = &in_hi[buf][q * 360 + toff];
            const unsigned* bh1 = &in_hi[buf][(q + 4) * 360 + toff];
            const unsigned* bl0 = &in_lo[buf][q * 360 + toff];
            const unsigned* bl1 = &in_lo[buf][(q + 4) * 360 + toff];
#pragma unroll
            for (int nt = 0; nt < NT; nt++) {
                unsigned bhi[2] = { bh0[pixoff[nt]], bh1[pixoff[nt]] };
                unsigned blo[2] = { bl0[pixoff[nt]], bl1[pixoff[nt]] };
#pragma unroll
                for (int mt = 0; mt < MT; mt++) {
                    mma16(acc[mt][nt], (const unsigned*)&ahi[mt], bhi);
                    mma16(acc[mt][nt], (const unsigned*)&ahi[mt], blo);
                    mma16(acc[mt][nt], (const unsigned*)&alo[mt], bhi);
                }
            }
        }
        __syncthreads();
    }

    // ---- epilogue ----
#pragma unroll
    for (int mt = 0; mt < MT; mt++) {
#pragma unroll
        for (int half = 0; half < 2; half++) {
            int co = cobase + cowb + mt * 16 + g + half * 8;
            if (co >= Cout) continue;
            float bs = bias ? bias[co] : 0.f;
            float* op = out + (long)r * o_rs + (long)b * obs + (long)co * HWp;
#pragma unroll
            for (int nt = 0; nt < NT; nt++) {
                int px = pwb + nt * 8 + 2 * q;
                int gp = (ty0 + (px >> 4)) * Wdim + tx0 + (px & 15);
                float v0 = acc[mt][nt][half * 2] + bs;
                float v1 = acc[mt][nt][half * 2 + 1] + bs;
                if (act) { v0 = tanhf(v0); v1 = tanhf(v1); }
                op[gp] = v0; op[gp + 1] = v1;
            }
        }
    }
}

// =============== FFMA fallback conv (small Cout paths) ===============
template <int CB, int ACT>
__global__ void __launch_bounds__(256) convk(
    const float* __restrict__ in0, int n0, long c0s, long b0s, long r0s,
    const float* __restrict__ in1, int n1, long c1s, long b1s, long r1s,
    const float* __restrict__ in2, int n2, long c2s, long b2s, long r2s,
    const float* __restrict__ wgt, int Cw,
    const float* __restrict__ bias,
    const float* __restrict__ radd, long radd_rs, long radd_bs, int ring_s,
    float* __restrict__ out, long o_rs, long obs,
    int Cin, int Cout, int nCo)
{
    __shared__ float tile[2][34 * 34];
    __shared__ float wsm[2][CB][9];

    int z = blockIdx.z;
    int cb = z % nCo;
    int zb = z / nCo;
    int b = zb % Bn;
    int r = zb / Bn;
    int cobase = cb * CB;

    int tid = threadIdx.x;
    int txc = tid & 15, tyr = tid >> 4;
    int x0 = blockIdx.x * 32, y0 = blockIdx.y * 32;

    int goff[5]; bool gok[5];
#pragma unroll
    for (int j = 0; j < 5; j++) {
        int i = tid + j * 256;
        int rr = i / 34, cc = i - rr * 34;
        int gy = y0 + rr - 1, gx = x0 + cc - 1;
        gok[j] = (i < 34 * 34) && (gy >= 0) && (gy < Hdim) && (gx >= 0) && (gx < Wdim);
        goff[j] = gy * Wdim + gx;
    }
    bool wldr = tid < CB * 9;
    int wco = tid / 9, wk = tid - wco * 9;
    bool wok = wldr && (cobase + wco < Cout);
    long wbase = ((long)(cobase + wco) * Cw) * 9 + wk;

    float acc[CB][4];
#pragma unroll
    for (int co = 0; co < CB; co++)
#pragma unroll
        for (int qq = 0; qq < 4; qq++) acc[co][qq] = 0.f;

    auto load_cin = [&](int cin, int p) {
        const float* src;
        if (cin < n0)           src = in0 + (long)b * b0s + (long)r * r0s + (long)cin * c0s;
        else if (cin < n0 + n1) src = in1 + (long)b * b1s + (long)r * r1s + (long)(cin - n0) * c1s;
        else                    src = in2 + (long)b * b2s + (long)r * r2s + (long)(cin - n0 - n1) * c2s;
#pragma unroll
        for (int j = 0; j < 4; j++)
            tile[p][tid + j * 256] = gok[j] ? src[goff[j]] : 0.f;
        if (tid + 1024 < 34 * 34)
            tile[p][tid + 1024] = gok[4] ? src[goff[4]] : 0.f;
        if (wldr)
            wsm[p][wco][wk] = wok ? wgt[wbase + (long)cin * 9] : 0.f;
    };

    load_cin(0, 0);
    __syncthreads();

    for (int cin = 0; cin < Cin; cin++) {
        int p = cin & 1;
        if (cin + 1 < Cin) load_cin(cin + 1, p ^ 1);

        float v[4][4];
#pragma unroll
        for (int rr = 0; rr < 4; rr++)
#pragma unroll
            for (int cc = 0; cc < 4; cc++)
                v[rr][cc] = tile[p][(2 * tyr + rr) * 34 + 2 * txc + cc];

#pragma unroll
        for (int co = 0; co < CB; co++) {
#pragma unroll
            for (int k = 0; k < 9; k++) {
                float w = wsm[p][co][k];
                int dy = k / 3, dx = k % 3;
                acc[co][0] = fmaf(v[dy][dx],         w, acc[co][0]);
                acc[co][1] = fmaf(v[dy][dx + 1],     w, acc[co][1]);
                acc[co][2] = fmaf(v[dy + 1][dx],     w, acc[co][2]);
                acc[co][3] = fmaf(v[dy + 1][dx + 1], w, acc[co][3]);
            }
        }
        __syncthreads();
    }

    int ox = x0 + 2 * txc, oy = y0 + 2 * tyr;
    long p0 = (long)oy * Wdim + ox;
    int pr = (radd && ring_s >= 0) ? (ring_s + r) % Tn : r;
#pragma unroll
    for (int co = 0; co < CB; co++) {
        int c = cobase + co;
        if (c >= Cout) continue;
        float bs = bias ? bias[c] : 0.f;
        float v0 = acc[co][0] + bs, v1 = acc[co][1] + bs;
        float v2 = acc[co][2] + bs, v3 = acc[co][3] + bs;
        if (radd) {
            const float* ra = radd + (long)pr * radd_rs + (long)b * radd_bs + (long)c * HWp + p0;
            v0 += ra[0]; v1 += ra[1]; v2 += ra[Wdim]; v3 += ra[Wdim + 1];
        }
        if (ACT == 1) { v0 = tanhf(v0); v1 = tanhf(v1); v2 = tanhf(v2); v3 = tanhf(v3); }
        float* o = out + (long)r * o_rs + (long)b * obs + (long)c * HWp + p0;
        o[0] = v0; o[1] = v1; o[Wdim] = v2; o[Wdim + 1] = v3;
    }
}

// ---------------- LSTM pointwise gate update ----------------
__global__ void lstm_k(const float* __restrict__ z, const float* __restrict__ cin, long cin_bs,
                       float* __restrict__ hout, long h_bs, float* __restrict__ cout_, long c_bs,
                       float* __restrict__ hout2, long h2_bs, int C)
{
    long total = (long)Bn * C * HWp;
    long idx = (long)blockIdx.x * blockDim.x + threadIdx.x;
    if (idx >= total) return;
    long CHW = (long)C * HWp;
    int b = (int)(idx / CHW);
    long r = idx - (long)b * CHW;
    const float* zb = z + (long)b * 4 * CHW;
    float zi = zb[r], zf = zb[CHW + r], zo = zb[2 * CHW + r], zg = zb[3 * CHW + r];
    float c = cin[(long)b * cin_bs + r];
    float c2 = sigm(zf) * c + sigm(zi) * tanhf(zg);
    float h2 = sigm(zo) * tanhf(c2);
    hout[(long)b * h_bs + r] = h2;
    cout_[(long)b * c_bs + r] = c2;
    if (hout2) hout2[(long)b * h2_bs + r] = h2;
}

// ---------------- input attention softmax + compounding reweight ----------------
__global__ void inattn_k(const float* __restrict__ score, float* __restrict__ xx)
{
    int idx = blockIdx.x * blockDim.x + threadIdx.x;
    if (idx >= Bn * HWp) return;
    int b = idx / HWp, p = idx - b * HWp;
    const float* sc = score + (long)b * Dn * HWp + p;
    float s[Dn];
    float m = -1e30f;
#pragma unroll
    for (int k = 0; k < Dn; k++) { s[k] = sc[(long)k * HWp]; m = fmaxf(m, s[k]); }
    float sum = 0.f;
#pragma unroll
    for (int k = 0; k < Dn; k++) { s[k] = __expf(s[k] - m); sum += s[k]; }
    float inv = 1.f / sum;
    float* xb = xx + (long)b * Tn * Dn * HWp + p;
#pragma unroll
    for (int k = 0; k < Dn; k++) {
        float a = s[k] * inv;
        for (int t = 0; t < Tn; t++) xb[((long)t * Dn + k) * HWp] *= a;
    }
}

// ---------------- temporal attention softmax + weighted sum ----------------
__global__ void tattn_k(const float* __restrict__ score, const float* __restrict__ hs1,
                        float* __restrict__ hatt, int s)
{
    int idx = blockIdx.x * blockDim.x + threadIdx.x;
    if (idx >= Bn * HWp) return;
    int b = idx / HWp, p = idx - b * HWp;
    const float* sc = score + (long)b * Tn * HWp + p;
    float bt[Tn];
    float m = -1e30f;
#pragma unroll
    for (int t = 0; t < Tn; t++) { bt[t] = sc[(long)t * HWp]; m = fmaxf(m, bt[t]); }
    float sum = 0.f;
#pragma unroll
    for (int t = 0; t < Tn; t++) { bt[t] = __expf(bt[t] - m); sum += bt[t]; }
    float inv = 1.f / sum;
    float acc[64];
#pragma unroll
    for (int c = 0; c < 64; c++) acc[c] = 0.f;
    for (int t = 0; t < Tn; t++) {
        int phys = (s + t) % Tn;
        const float* hb = hs1 + ((long)b * Tn + phys) * 64 * HWp + p;
        float w = bt[t] * inv;
#pragma unroll
        for (int c = 0; c < 64; c++) acc[c] = fmaf(hb[(long)c * HWp], w, acc[c]);
    }
    float* ob = hatt + (long)b * 64 * HWp + p;
#pragma unroll
    for (int c = 0; c < 64; c++) ob[(long)c * HWp] = acc[c];
}

// ---------------- host side ----------------
struct Seg { const float* p; int n; long cs, bs, rs; };
static inline Seg mkseg(const float* p, int n, long cs, long bs, long rs) {
    Seg s; s.p = p; s.n = n; s.cs = cs; s.bs = bs; s.rs = rs; return s;
}

static void conv(int CB, int ACT, Seg a, Seg b, Seg c,
                 const float* w, int Cw, const float* bias,
                 const float* radd, long rrs, long rbs, int ring_s,
                 float* out, long ors, long obs, int Cin, int Cout, int R)
{
    int nCo = (Cout + CB - 1) / CB;
    dim3 grid(Wdim / 32, Hdim / 32, R * Bn * nCo);
#define CARGS a.p, a.n, a.cs, a.bs, a.rs, b.p, b.n, b.cs, b.bs, b.rs, c.p, c.n, c.cs, c.bs, c.rs, \
              w, Cw, bias, radd, rrs, rbs, ring_s, out, ors, obs, Cin, Cout, nCo
    if (CB == 8 && ACT == 1) convk<8, 1><<<grid, 256>>>(CARGS);
    else if (CB == 8)        convk<8, 0><<<grid, 256>>>(CARGS);
    else                     convk<1, 0><<<grid, 256>>>(CARGS);
#undef CARGS
}

static void mconv(int MBLK, Seg a, Seg b, Seg c,
                  const unsigned* whi, const unsigned* wlo, int MTall,
                  const float* bias, int act,
                  float* out, long ors, long obs, int Cin, int Cout, int R)
{
    dim3 grid(64, (Cout + MBLK - 1) / MBLK, R * Bn);
#define MARGS a.p, a.n, a.cs, a.bs, a.rs, b.p, b.n, b.cs, b.bs, b.rs, c.p, c.n, c.cs, c.bs, c.rs, \
              whi, wlo, MTall, bias, act, out, ors, obs, Cin, Cout
    if (MBLK == 64)       mmaconv<64, 4><<<grid, 256>>>(MARGS);
    else if (MBLK == 32)  mmaconv<32, 8><<<grid, 256>>>(MARGS);
    else                  mmaconv<16, 8><<<grid, 256>>>(MARGS);
#undef MARGS
}

extern "C" void kernel_launch(void* const* d_in, const int* in_sizes, int n_in,
                              void* d_out, int out_size)
{
    const float* x      = (const float*)d_in[0];
    const float* h0     = (const float*)d_in[1];
    const float* c0     = (const float*)d_in[2];
    const float* h1     = (const float*)d_in[3];
    const float* c1     = (const float*)d_in[4];
    const float* w_enc0 = (const float*)d_in[5];
    const float* b_enc0 = (const float*)d_in[6];
    const float* w_enc1 = (const float*)d_in[7];
    const float* b_enc1 = (const float*)d_in[8];
    const float* w_dec0 = (const float*)d_in[9];
    const float* b_dec0 = (const float*)d_in[10];
    const float* w_dec1 = (const float*)d_in[11];
    const float* b_dec1 = (const float*)d_in[12];
    const float* wa1    = (const float*)d_in[13];
    const float* ba1    = (const float*)d_in[14];
    const float* wa2    = (const float*)d_in[15];
    const float* ba2    = (const float*)d_in[16];
    const float* wt1    = (const float*)d_in[17];
    const float* bt1    = (const float*)d_in[18];
    const float* wt2    = (const float*)d_in[19];
    const float* bt2    = (const float*)d_in[20];

    float *xx, *hs0, *cs0, *hs1, *cs1, *score, *hid, *z, *hatt, *tc;
    unsigned *whi, *wlo;
    cudaGetSymbolAddress((void**)&xx, g_xx);
    cudaGetSymbolAddress((void**)&hs0, g_hs0);
    cudaGetSymbolAddress((void**)&cs0, g_cs0);
    cudaGetSymbolAddress((void**)&hs1, g_hs1);
    cudaGetSymbolAddress((void**)&cs1, g_cs1);
    cudaGetSymbolAddress((void**)&score, g_score);
    cudaGetSymbolAddress((void**)&hid, g_hid);
    cudaGetSymbolAddress((void**)&z, g_z);
    cudaGetSymbolAddress((void**)&hatt, g_hatt);
    cudaGetSymbolAddress((void**)&tc, g_tc);
    cudaGetSymbolAddress((void**)&whi, g_whi);
    cudaGetSymbolAddress((void**)&wlo, g_wlo);

    cudaMemcpyAsync(xx, x, sizeof(float) * (size_t)Bn * Tn * Dn * HWp,
                    cudaMemcpyDeviceToDevice);

    // ---- pre-pack all mma weights (bf16 hi/lo, fragment order) ----
    const int PT = 256;
    wprep<<<(SZ_ENC1  + PT - 1) / PT, PT>>>(w_enc1,   65, 65, 256, 16, 5,  whi + OFF_ENC1,  wlo + OFF_ENC1);
    wprep<<<(SZ_DEC0  + PT - 1) / PT, PT>>>(w_dec0,   65, 65, 256, 16, 5,  whi + OFF_DEC0,  wlo + OFF_DEC0);
    wprep<<<(SZ_WA1   + PT - 1) / PT, PT>>>(wa1,      12, 12, 32,  2,  1,  whi + OFF_WA1,   wlo + OFF_WA1);
    wprep<<<(SZ_WT1HC + PT - 1) / PT, PT>>>(wt1 + 9, 129, 128, 32, 2,  8,  whi + OFF_WT1HC, wlo + OFF_WT1HC);
    wprep<<<(SZ_ENC0  + PT - 1) / PT, PT>>>(w_enc0,   11, 11, 4,   1,  1,  whi + OFF_ENC0,  wlo + OFF_ENC0);
    wprep<<<(SZ_DEC1  + PT - 1) / PT, PT>>>(w_dec1,   65, 65, 4,   1,  5,  whi + OFF_DEC1,  wlo + OFF_DEC1);

    Seg none = mkseg(nullptr, 0, 0, 0, 0);
    const int thr = 256;
    const long HID_RS = (long)Bn * 32 * HWp;

    // ======== encoder layer 0 (hidden 1), compounding input attention ========
    for (int t = 0; t < Tn; t++) {
        const float* hp = (t == 0) ? h0 : hs0 + (long)(t - 1) * HWp;
        long hbs        = (t == 0) ? (long)HWp : (long)Tn * HWp;
        const float* cp = (t == 0) ? c0 : cs0 + (long)(t - 1) * HWp;
        long cbs = hbs;

        mconv(32,
              mkseg(xx, Tn, (long)Dn * HWp, (long)Tn * Dn * HWp, (long)HWp),
              mkseg(hp, 1, 0, hbs, 0),
              mkseg(cp, 1, 0, cbs, 0),
              whi + OFF_WA1, wlo + OFF_WA1, 2, ba1, 1,
              hid, HID_RS, 32L * HWp, 12, 32, Dn);
        conv(1, 0,
             mkseg(hid, 32, HWp, 32L * HWp, HID_RS), none, none,
             wa2, 32, ba2, nullptr, 0, 0, -1,
             score, (long)HWp, (long)Dn * HWp, 32, 1, Dn);
        inattn_k<<<(Bn * HWp + thr - 1) / thr, thr>>>(score, xx);

        mconv(16,
              mkseg(xx + (long)t * Dn * HWp, Dn, (long)HWp, (long)Tn * Dn * HWp, 0),
              mkseg(hp, 1, 0, hbs, 0), none,
              whi + OFF_ENC0, wlo + OFF_ENC0, 1, b_enc0, 0,
              z, 0, 4L * HWp, 11, 4, 1);
        long n = (long)Bn * HWp;
        lstm_k<<<(n + thr - 1) / thr, thr>>>(z, cp, cbs,
                                             hs0 + (long)t * HWp, (long)Tn * HWp,
                                             cs0 + (long)t * HWp, (long)Tn * HWp,
                                             nullptr, 0, 1);
    }

    // ======== encoder layer 1 (65->256) ========
    for (int t = 0; t < Tn; t++) {
        const float* hp = (t == 0) ? h1 : hs1 + (long)(t - 1) * 64 * HWp;
        long hbs        = (t == 0) ? 64L * HWp : (long)Tn * 64 * HWp;
        const float* cp = (t == 0) ? c1 : cs1 + (long)(t - 1) * 64 * HWp;

        mconv(64,
              mkseg(hs0 + (long)t * HWp, 1, 0, (long)Tn * HWp, 0),
              mkseg(hp, 64, HWp, hbs, 0), none,
              whi + OFF_ENC1, wlo + OFF_ENC1, 16, b_enc1, 0,
              z, 0, 256L * HWp, 65, 256, 1);
        long n = (long)Bn * 64 * HWp;
        lstm_k<<<(n + thr - 1) / thr, thr>>>(z, cp, hbs,
                                             hs1 + (long)t * 64 * HWp, (long)Tn * 64 * HWp,
                                             cs1 + (long)t * 64 * HWp, (long)Tn * 64 * HWp,
                                             nullptr, 0, 64);
    }

    // ======== temporal-attn h/c conv cache (128->32) all slots ========
    mconv(32,
          mkseg(hs1, 64, HWp, (long)Tn * 64 * HWp, 64L * HWp),
          mkseg(cs1, 64, HWp, (long)Tn * 64 * HWp, 64L * HWp), none,
          whi + OFF_WT1HC, wlo + OFF_WT1HC, 2, bt1, 0,
          tc, HID_RS, 32L * HWp, 128, 32, Tn);

    // ======== decoder ========
    float* out = (float*)d_out;
    for (int s = 0; s < 5; s++) {
        const float* yp; long ybs;
        if (s == 0) { yp = x + 90L * HWp; ybs = 100L * HWp; }
        else        { yp = hs0 + (long)(s - 1) * HWp; ybs = (long)Tn * HWp; }

        conv(8, 1,
             mkseg(yp, 1, 0, ybs, 0), none, none,
             wt1, 129, nullptr, tc, HID_RS, 32L * HWp, s,
             hid, HID_RS, 32L * HWp, 1, 32, Tn);
        conv(1, 0,
             mkseg(hid, 32, HWp, 32L * HWp, HID_RS), none, none,
             wt2, 32, bt2, nullptr, 0, 0, -1,
             score, (long)HWp, (long)Tn * HWp, 32, 1, Tn);
        tattn_k<<<(Bn * HWp + thr - 1) / thr, thr>>>(score, hs1, hatt, s);

        int pl = (s + 9) % Tn;

        mconv(64,
              mkseg(yp, 1, 0, ybs, 0),
              mkseg(hatt, 64, HWp, 64L * HWp, 0), none,
              whi + OFF_DEC0, wlo + OFF_DEC0, 16, b_dec0, 0,
              z, 0, 256L * HWp, 65, 256, 1);
        long n64 = (long)Bn * 64 * HWp;
        lstm_k<<<(n64 + thr - 1) / thr, thr>>>(z, cs1 + (long)pl * 64 * HWp, (long)Tn * 64 * HWp,
                                               hs1 + (long)s * 64 * HWp, (long)Tn * 64 * HWp,
                                               cs1 + (long)s * 64 * HWp, (long)Tn * 64 * HWp,
                                               nullptr, 0, 64);

        mconv(32,
              mkseg(hs1 + (long)s * 64 * HWp, 64, HWp, (long)Tn * 64 * HWp, 0),
              mkseg(cs1 + (long)s * 64 * HWp, 64, HWp, (long)Tn * 64 * HWp, 0), none,
              whi + OFF_WT1HC, wlo + OFF_WT1HC, 2, bt1, 0,
              tc + (long)s * HID_RS, 0, 32L * HWp, 128, 32, 1);

        mconv(16,
              mkseg(hs1 + (long)s * 64 * HWp, 64, HWp, (long)Tn * 64 * HWp, 0),
              mkseg(hs0 + (long)pl * HWp, 1, 0, (long)Tn * HWp, 0), none,
              whi + OFF_DEC1, wlo + OFF_DEC1, 1, b_dec1, 0,
              z, 0, 4L * HWp, 65, 4, 1);
        long n1 = (long)Bn * HWp;
        lstm_k<<<(n1 + thr - 1) / thr, thr>>>(z, cs0 + (long)pl * HWp, (long)Tn * HWp,
                                              hs0 + (long)s * HWp, (long)Tn * HWp,
                                              cs0 + (long)s * HWp, (long)Tn * HWp,
                                              out + (long)s * HWp, 5L * HWp, 1);
    }
}

// round 12
// speedup vs baseline: 1.1462x; 1.1462x over previous
#include <cuda_runtime.h>
#include <cuda_bf16.h>
#include <math.h>

#define HWp 16384
#define Hdim 128
#define Wdim 128
#define Bn 8
#define Tn 10
#define Dn 10

// ---------------- scratch state (device globals) ----------------
__device__ float g_xx[(size_t)Bn*Tn*Dn*HWp];
__device__ float g_hs0[(size_t)Bn*Tn*HWp];
__device__ float g_cs0[(size_t)Bn*Tn*HWp];
__device__ float g_hs1[(size_t)Bn*Tn*64*HWp];
__device__ float g_cs1[(size_t)Bn*Tn*64*HWp];
__device__ float g_score[(size_t)Bn*Tn*HWp];
__device__ float g_hid[(size_t)Tn*Bn*32*HWp];
__device__ float g_z[(size_t)Bn*256*HWp];
__device__ float g_hatt[(size_t)Bn*64*HWp];
__device__ float g_tc[(size_t)Tn*Bn*32*HWp];

// pre-packed fragment-order bf16x2 weights (hi/lo)
#define WTOT 173952
__device__ __align__(16) unsigned g_whi[WTOT];
__device__ __align__(16) unsigned g_wlo[WTOT];
// layout [(cb*9+tap)*MTall + mtile]*128 + lane*4 + j
#define OFF_ENC1  0
#define SZ_ENC1   73728      // nCh=4 (ci 1..64), MTall=16
#define OFF_DEC0  73728
#define SZ_DEC0   73728      // nCh=4 (ci 1..64), MTall=16
#define OFF_WA1   147456
#define SZ_WA1    2304       // nCh=1, MTall=2
#define OFF_WT1HC 149760
#define SZ_WT1HC  18432      // nCh=8, MTall=2
#define OFF_ENC0  168192
#define SZ_ENC0   1152       // nCh=1, MTall=1
#define OFF_DEC1  169344
#define SZ_DEC1   4608       // nCh=4 (ci 0..63), MTall=1

__device__ __forceinline__ float sigm(float x) { return 1.f / (1.f + __expf(-x)); }

__device__ __forceinline__ unsigned packbf(__nv_bfloat16 a, __nv_bfloat16 b) {
    return ((unsigned)__bfloat16_as_ushort(b) << 16) | __bfloat16_as_ushort(a);
}
__device__ __forceinline__ void splitbf(float v, __nv_bfloat16& h, __nv_bfloat16& l) {
    h = __float2bfloat16(v);
    l = __float2bfloat16(v - __bfloat162float(h));
}
__device__ __forceinline__ void mma16(float* c, const unsigned* a, const unsigned* b) {
    asm volatile("mma.sync.aligned.m16n8k16.row.col.f32.bf16.bf16.f32 "
        "{%0,%1,%2,%3}, {%4,%5,%6,%7}, {%8,%9}, {%0,%1,%2,%3};"
        : "+f"(c[0]), "+f"(c[1]), "+f"(c[2]), "+f"(c[3])
        : "r"(a[0]), "r"(a[1]), "r"(a[2]), "r"(a[3]), "r"(b[0]), "r"(b[1]));
}

// ---------------- weight pre-pack into m16n8k16 fragment order ----------------
__global__ void wprep(const float* __restrict__ wgt, int Cw, int Cin, int Cout,
                      int MTall, int nCh, unsigned* __restrict__ whi,
                      unsigned* __restrict__ wlo)
{
    int idx = blockIdx.x * blockDim.x + threadIdx.x;
    int total = nCh * 9 * MTall * 128;
    if (idx >= total) return;
    int li = idx & 127;
    int j = li & 3, ln = li >> 2;
    int f = idx >> 7;
    int mtile = f % MTall;
    int tap = (f / MTall) % 9;
    int cb = f / (MTall * 9);
    int g = ln >> 2, q = ln & 3;
    int co = mtile * 16 + g + (j & 1) * 8;
    int kb = 2 * q + (j >> 1) * 8;
    int ci0 = cb * 16 + kb;
    float w0 = 0.f, w1 = 0.f;
    if (co < Cout) {
        if (ci0 < Cin)     w0 = wgt[((long)co * Cw + ci0) * 9 + tap];
        if (ci0 + 1 < Cin) w1 = wgt[((long)co * Cw + ci0 + 1) * 9 + tap];
    }
    __nv_bfloat16 h0, l0, h1, l1;
    splitbf(w0, h0, l0);
    splitbf(w1, h1, l1);
    whi[idx] = packbf(h0, h1);
    wlo[idx] = packbf(l0, l1);
}

// =============== implicit-GEMM 3x3 conv, bf16 hi/lo split, m16n8k16 ===============
// SPLIT=3: hi/lo split (~fp32); SPLIT=1: plain bf16.
// Optional aux channel: one extra input channel convolved exactly in fp32 in
// the epilogue (weights wax[co*wstr + tap]) — removes Cin padding waste.
template <int MBLK, int WN, int SPLIT>
__global__ void __launch_bounds__(256) mmaconv(
    const float* __restrict__ in0, int n0, long c0s, long b0s, long r0s,
    const float* __restrict__ in1, int n1, long c1s, long b1s, long r1s,
    const float* __restrict__ in2, int n2, long c2s, long b2s, long r2s,
    const unsigned* __restrict__ whi, const unsigned* __restrict__ wlo, int MTall,
    const float* __restrict__ aux, long aux_bs,
    const float* __restrict__ wax, int wstr,
    const float* __restrict__ bias, int act,
    float* __restrict__ out, long o_rs, long obs, int Cin, int Cout)
{
    constexpr int WM = 8 / WN;
    constexpr int MT = MBLK / (16 * WM);
    constexpr int NT = 32 / WN;

    __shared__ unsigned in_hi[2][8 * 360];
    __shared__ unsigned in_lo[(SPLIT == 3) ? 2 : 1][(SPLIT == 3) ? 8 * 360 : 1];
    __shared__ float auxs[18 * 19];

    int b = blockIdx.z % Bn;
    int r = blockIdx.z / Bn;
    int cobase = blockIdx.y * MBLK;
    int ty0 = (blockIdx.x >> 3) * 16, tx0 = (blockIdx.x & 7) * 16;

    int tid = threadIdx.x;
    int wid = tid >> 5, lane = tid & 31;
    int g = lane >> 2, q = lane & 3;
    int cowb = (wid / WN) * (MT * 16);
    int pwb  = (wid % WN) * (NT * 8);

    int pixoff[NT];
#pragma unroll
    for (int nt = 0; nt < NT; nt++) {
        int px = pwb + nt * 8 + g;
        pixoff[nt] = (px >> 4) * 19 + (px & 15);
    }

    float acc[MT][NT][4];
#pragma unroll
    for (int mt = 0; mt < MT; mt++)
#pragma unroll
        for (int nt = 0; nt < NT; nt++)
#pragma unroll
            for (int i = 0; i < 4; i++) acc[mt][nt][i] = 0.f;

    // stage aux channel halo tile (fp32)
    if (aux) {
        for (int i = tid; i < 324; i += 256) {
            int rr = i / 18, cc = i - rr * 18;
            int gy = ty0 + rr - 1, gx = tx0 + cc - 1;
            float v = 0.f;
            if (gy >= 0 && gy < Hdim && gx >= 0 && gx < Wdim)
                v = aux[(long)b * aux_bs + gy * Wdim + gx];
            auxs[rr * 19 + cc] = v;
        }
    }

    auto ldci = [&](int cig, int go) -> float {
        if (cig >= Cin) return 0.f;
        const float* src;
        if (cig < n0)           src = in0 + (long)b * b0s + (long)r * r0s + (long)cig * c0s;
        else if (cig < n0 + n1) src = in1 + (long)b * b1s + (long)r * r1s + (long)(cig - n0) * c1s;
        else                    src = in2 + (long)b * b2s + (long)r * r2s + (long)(cig - n0 - n1) * c2s;
        return src[go];
    };
    auto stage = [&](int cb, int buf) {
#pragma unroll
        for (int jj = 0; jj < 11; jj++) {
            int i = tid + jj * 256;
            if (i >= 2592) continue;
            int cp = i / 324; int rem = i - cp * 324;
            int rr = rem / 18, cc = rem - rr * 18;
            int gy = ty0 + rr - 1, gx = tx0 + cc - 1;
            float v0 = 0.f, v1 = 0.f;
            if (gy >= 0 && gy < Hdim && gx >= 0 && gx < Wdim) {
                int go = gy * Wdim + gx;
                int ci0 = cb * 16 + 2 * cp;
                v0 = ldci(ci0, go);
                v1 = ldci(ci0 + 1, go);
            }
            __nv_bfloat16 h0, l0, h1, l1;
            splitbf(v0, h0, l0);
            splitbf(v1, h1, l1);
            int so = cp * 360 + rr * 19 + cc;
            in_hi[buf][so] = packbf(h0, h1);
            if (SPLIT == 3) in_lo[buf][so] = packbf(l0, l1);
        }
    };

    int nCh = (Cin + 15) >> 4;
    stage(0, 0);
    __syncthreads();

    for (int cb = 0; cb < nCh; cb++) {
        int buf = cb & 1;
        if (cb + 1 < nCh) stage(cb + 1, buf ^ 1);

        long wchunk = (long)cb * 9 * MTall * 128;
#pragma unroll
        for (int tap = 0; tap < 9; tap++) {
            int toff = (tap / 3) * 19 + (tap % 3);
            uint4 ahi[MT], alo[MT];
#pragma unroll
            for (int mt = 0; mt < MT; mt++) {
                int mtg = (cobase >> 4) + (cowb >> 4) + mt;
                long fb = wchunk + ((long)tap * MTall + mtg) * 128 + lane * 4;
                ahi[mt] = *(const uint4*)&whi[fb];
                if (SPLIT == 3) alo[mt] = *(const uint4*)&wlo[fb];
            }
            const unsigned* bh0 = &in_hi[buf][q * 360 + toff];
            const unsigned* bh1 = &in_hi[buf][(q + 4) * 360 + toff];
            const unsigned* bl0 = &in_lo[(SPLIT == 3) ? buf : 0][(SPLIT == 3) ? q * 360 + toff : 0];
            const unsigned* bl1 = &in_lo[(SPLIT == 3) ? buf : 0][(SPLIT == 3) ? (q + 4) * 360 + toff : 0];
#pragma unroll
            for (int nt = 0; nt < NT; nt++) {
                unsigned bhi[2] = { bh0[pixoff[nt]], bh1[pixoff[nt]] };
                unsigned blo[2];
                if (SPLIT == 3) { blo[0] = bl0[pixoff[nt]]; blo[1] = bl1[pixoff[nt]]; }
#pragma unroll
                for (int mt = 0; mt < MT; mt++) {
                    mma16(acc[mt][nt], (const unsigned*)&ahi[mt], bhi);
                    if (SPLIT == 3) {
                        mma16(acc[mt][nt], (const unsigned*)&ahi[mt], blo);
                        mma16(acc[mt][nt], (const unsigned*)&alo[mt], bhi);
                    }
                }
            }
        }
        __syncthreads();
    }

    // ---- epilogue (+ exact fp32 aux-channel conv) ----
#pragma unroll
    for (int mt = 0; mt < MT; mt++) {
#pragma unroll
        for (int half = 0; half < 2; half++) {
            int co = cobase + cowb + mt * 16 + g + half * 8;
            if (co >= Cout) continue;
            float bs = bias ? bias[co] : 0.f;
            float w9[9];
            if (aux) {
#pragma unroll
                for (int t9 = 0; t9 < 9; t9++) w9[t9] = wax[(long)co * wstr + t9];
            }
            float* op = out + (long)r * o_rs + (long)b * obs + (long)co * HWp;
#pragma unroll
            for (int nt = 0; nt < NT; nt++) {
                int px = pwb + nt * 8 + 2 * q;
                int pr = px >> 4, pc = px & 15;
                int gp = (ty0 + pr) * Wdim + tx0 + pc;
                float v0 = acc[mt][nt][half * 2] + bs;
                float v1 = acc[mt][nt][half * 2 + 1] + bs;
                if (aux) {
#pragma unroll
                    for (int dy = 0; dy < 3; dy++)
#pragma unroll
                        for (int dx = 0; dx < 3; dx++) {
                            float w = w9[dy * 3 + dx];
                            v0 = fmaf(w, auxs[(pr + dy) * 19 + pc + dx], v0);
                            v1 = fmaf(w, auxs[(pr + dy) * 19 + pc + 1 + dx], v1);
                        }
                }
                if (act) { v0 = tanhf(v0); v1 = tanhf(v1); }
                op[gp] = v0; op[gp + 1] = v1;
            }
        }
    }
}

// =============== FFMA fallback conv (small Cout paths) ===============
template <int CB, int ACT>
__global__ void __launch_bounds__(256) convk(
    const float* __restrict__ in0, int n0, long c0s, long b0s, long r0s,
    const float* __restrict__ in1, int n1, long c1s, long b1s, long r1s,
    const float* __restrict__ in2, int n2, long c2s, long b2s, long r2s,
    const float* __restrict__ wgt, int Cw,
    const float* __restrict__ bias,
    const float* __restrict__ radd, long radd_rs, long radd_bs, int ring_s,
    float* __restrict__ out, long o_rs, long obs,
    int Cin, int Cout, int nCo)
{
    __shared__ float tile[2][34 * 34];
    __shared__ float wsm[2][CB][9];

    int z = blockIdx.z;
    int cb = z % nCo;
    int zb = z / nCo;
    int b = zb % Bn;
    int r = zb / Bn;
    int cobase = cb * CB;

    int tid = threadIdx.x;
    int txc = tid & 15, tyr = tid >> 4;
    int x0 = blockIdx.x * 32, y0 = blockIdx.y * 32;

    int goff[5]; bool gok[5];
#pragma unroll
    for (int j = 0; j < 5; j++) {
        int i = tid + j * 256;
        int rr = i / 34, cc = i - rr * 34;
        int gy = y0 + rr - 1, gx = x0 + cc - 1;
        gok[j] = (i < 34 * 34) && (gy >= 0) && (gy < Hdim) && (gx >= 0) && (gx < Wdim);
        goff[j] = gy * Wdim + gx;
    }
    bool wldr = tid < CB * 9;
    int wco = tid / 9, wk = tid - wco * 9;
    bool wok = wldr && (cobase + wco < Cout);
    long wbase = ((long)(cobase + wco) * Cw) * 9 + wk;

    float acc[CB][4];
#pragma unroll
    for (int co = 0; co < CB; co++)
#pragma unroll
        for (int qq = 0; qq < 4; qq++) acc[co][qq] = 0.f;

    auto load_cin = [&](int cin, int p) {
        const float* src;
        if (cin < n0)           src = in0 + (long)b * b0s + (long)r * r0s + (long)cin * c0s;
        else if (cin < n0 + n1) src = in1 + (long)b * b1s + (long)r * r1s + (long)(cin - n0) * c1s;
        else                    src = in2 + (long)b * b2s + (long)r * r2s + (long)(cin - n0 - n1) * c2s;
#pragma unroll
        for (int j = 0; j < 4; j++)
            tile[p][tid + j * 256] = gok[j] ? src[goff[j]] : 0.f;
        if (tid + 1024 < 34 * 34)
            tile[p][tid + 1024] = gok[4] ? src[goff[4]] : 0.f;
        if (wldr)
            wsm[p][wco][wk] = wok ? wgt[wbase + (long)cin * 9] : 0.f;
    };

    load_cin(0, 0);
    __syncthreads();

    for (int cin = 0; cin < Cin; cin++) {
        int p = cin & 1;
        if (cin + 1 < Cin) load_cin(cin + 1, p ^ 1);

        float v[4][4];
#pragma unroll
        for (int rr = 0; rr < 4; rr++)
#pragma unroll
            for (int cc = 0; cc < 4; cc++)
                v[rr][cc] = tile[p][(2 * tyr + rr) * 34 + 2 * txc + cc];

#pragma unroll
        for (int co = 0; co < CB; co++) {
#pragma unroll
            for (int k = 0; k < 9; k++) {
                float w = wsm[p][co][k];
                int dy = k / 3, dx = k % 3;
                acc[co][0] = fmaf(v[dy][dx],         w, acc[co][0]);
                acc[co][1] = fmaf(v[dy][dx + 1],     w, acc[co][1]);
                acc[co][2] = fmaf(v[dy + 1][dx],     w, acc[co][2]);
                acc[co][3] = fmaf(v[dy + 1][dx + 1], w, acc[co][3]);
            }
        }
        __syncthreads();
    }

    int ox = x0 + 2 * txc, oy = y0 + 2 * tyr;
    long p0 = (long)oy * Wdim + ox;
    int pr = (radd && ring_s >= 0) ? (ring_s + r) % Tn : r;
#pragma unroll
    for (int co = 0; co < CB; co++) {
        int c = cobase + co;
        if (c >= Cout) continue;
        float bs = bias ? bias[c] : 0.f;
        float v0 = acc[co][0] + bs, v1 = acc[co][1] + bs;
        float v2 = acc[co][2] + bs, v3 = acc[co][3] + bs;
        if (radd) {
            const float* ra = radd + (long)pr * radd_rs + (long)b * radd_bs + (long)c * HWp + p0;
            v0 += ra[0]; v1 += ra[1]; v2 += ra[Wdim]; v3 += ra[Wdim + 1];
        }
        if (ACT == 1) { v0 = tanhf(v0); v1 = tanhf(v1); v2 = tanhf(v2); v3 = tanhf(v3); }
        float* o = out + (long)r * o_rs + (long)b * obs + (long)c * HWp + p0;
        o[0] = v0; o[1] = v1; o[Wdim] = v2; o[Wdim + 1] = v3;
    }
}

// ---------------- LSTM pointwise gate update ----------------
__global__ void lstm_k(const float* __restrict__ z, const float* __restrict__ cin, long cin_bs,
                       float* __restrict__ hout, long h_bs, float* __restrict__ cout_, long c_bs,
                       float* __restrict__ hout2, long h2_bs, int C)
{
    long total = (long)Bn * C * HWp;
    long idx = (long)blockIdx.x * blockDim.x + threadIdx.x;
    if (idx >= total) return;
    long CHW = (long)C * HWp;
    int b = (int)(idx / CHW);
    long r = idx - (long)b * CHW;
    const float* zb = z + (long)b * 4 * CHW;
    float zi = zb[r], zf = zb[CHW + r], zo = zb[2 * CHW + r], zg = zb[3 * CHW + r];
    float c = cin[(long)b * cin_bs + r];
    float c2 = sigm(zf) * c + sigm(zi) * tanhf(zg);
    float h2 = sigm(zo) * tanhf(c2);
    hout[(long)b * h_bs + r] = h2;
    cout_[(long)b * c_bs + r] = c2;
    if (hout2) hout2[(long)b * h2_bs + r] = h2;
}

// ---------------- input attention softmax + compounding reweight ----------------
__global__ void inattn_k(const float* __restrict__ score, float* __restrict__ xx)
{
    int idx = blockIdx.x * blockDim.x + threadIdx.x;
    if (idx >= Bn * HWp) return;
    int b = idx / HWp, p = idx - b * HWp;
    const float* sc = score + (long)b * Dn * HWp + p;
    float s[Dn];
    float m = -1e30f;
#pragma unroll
    for (int k = 0; k < Dn; k++) { s[k] = sc[(long)k * HWp]; m = fmaxf(m, s[k]); }
    float sum = 0.f;
#pragma unroll
    for (int k = 0; k < Dn; k++) { s[k] = __expf(s[k] - m); sum += s[k]; }
    float inv = 1.f / sum;
    float* xb = xx + (long)b * Tn * Dn * HWp + p;
#pragma unroll
    for (int k = 0; k < Dn; k++) {
        float a = s[k] * inv;
        for (int t = 0; t < Tn; t++) xb[((long)t * Dn + k) * HWp] *= a;
    }
}

// ---------------- temporal attention softmax + weighted sum ----------------
__global__ void tattn_k(const float* __restrict__ score, const float* __restrict__ hs1,
                        float* __restrict__ hatt, int s)
{
    int idx = blockIdx.x * blockDim.x + threadIdx.x;
    if (idx >= Bn * HWp) return;
    int b = idx / HWp, p = idx - b * HWp;
    const float* sc = score + (long)b * Tn * HWp + p;
    float bt[Tn];
    float m = -1e30f;
#pragma unroll
    for (int t = 0; t < Tn; t++) { bt[t] = sc[(long)t * HWp]; m = fmaxf(m, bt[t]); }
    float sum = 0.f;
#pragma unroll
    for (int t = 0; t < Tn; t++) { bt[t] = __expf(bt[t] - m); sum += bt[t]; }
    float inv = 1.f / sum;
    float acc[64];
#pragma unroll
    for (int c = 0; c < 64; c++) acc[c] = 0.f;
    for (int t = 0; t < Tn; t++) {
        int phys = (s + t) % Tn;
        const float* hb = hs1 + ((long)b * Tn + phys) * 64 * HWp + p;
        float w = bt[t] * inv;
#pragma unroll
        for (int c = 0; c < 64; c++) acc[c] = fmaf(hb[(long)c * HWp], w, acc[c]);
    }
    float* ob = hatt + (long)b * 64 * HWp + p;
#pragma unroll
    for (int c = 0; c < 64; c++) ob[(long)c * HWp] = acc[c];
}

// ---------------- host side ----------------
struct Seg { const float* p; int n; long cs, bs, rs; };
static inline Seg mkseg(const float* p, int n, long cs, long bs, long rs) {
    Seg s; s.p = p; s.n = n; s.cs = cs; s.bs = bs; s.rs = rs; return s;
}

static void conv(int CB, int ACT, Seg a, Seg b, Seg c,
                 const float* w, int Cw, const float* bias,
                 const float* radd, long rrs, long rbs, int ring_s,
                 float* out, long ors, long obs, int Cin, int Cout, int R)
{
    int nCo = (Cout + CB - 1) / CB;
    dim3 grid(Wdim / 32, Hdim / 32, R * Bn * nCo);
#define CARGS a.p, a.n, a.cs, a.bs, a.rs, b.p, b.n, b.cs, b.bs, b.rs, c.p, c.n, c.cs, c.bs, c.rs, \
              w, Cw, bias, radd, rrs, rbs, ring_s, out, ors, obs, Cin, Cout, nCo
    if (CB == 8 && ACT == 1) convk<8, 1><<<grid, 256>>>(CARGS);
    else if (CB == 8)        convk<8, 0><<<grid, 256>>>(CARGS);
    else                     convk<1, 0><<<grid, 256>>>(CARGS);
#undef CARGS
}

static void mconv(int MBLK, int SPLIT, Seg a, Seg b, Seg c,
                  const unsigned* whi, const unsigned* wlo, int MTall,
                  const float* aux, long aux_bs, const float* wax, int wstr,
                  const float* bias, int act,
                  float* out, long ors, long obs, int Cin, int Cout, int R)
{
    dim3 grid(64, (Cout + MBLK - 1) / MBLK, R * Bn);
#define MARGS a.p, a.n, a.cs, a.bs, a.rs, b.p, b.n, b.cs, b.bs, b.rs, c.p, c.n, c.cs, c.bs, c.rs, \
              whi, wlo, MTall, aux, aux_bs, wax, wstr, bias, act, out, ors, obs, Cin, Cout
    if (MBLK == 64)                     mmaconv<64, 4, 3><<<grid, 256>>>(MARGS);
    else if (MBLK == 32 && SPLIT == 1)  mmaconv<32, 8, 1><<<grid, 256>>>(MARGS);
    else if (MBLK == 32)                mmaconv<32, 8, 3><<<grid, 256>>>(MARGS);
    else                                mmaconv<16, 8, 3><<<grid, 256>>>(MARGS);
#undef MARGS
}

extern "C" void kernel_launch(void* const* d_in, const int* in_sizes, int n_in,
                              void* d_out, int out_size)
{
    const float* x      = (const float*)d_in[0];
    const float* h0     = (const float*)d_in[1];
    const float* c0     = (const float*)d_in[2];
    const float* h1     = (const float*)d_in[3];
    const float* c1     = (const float*)d_in[4];
    const float* w_enc0 = (const float*)d_in[5];
    const float* b_enc0 = (const float*)d_in[6];
    const float* w_enc1 = (const float*)d_in[7];
    const float* b_enc1 = (const float*)d_in[8];
    const float* w_dec0 = (const float*)d_in[9];
    const float* b_dec0 = (const float*)d_in[10];
    const float* w_dec1 = (const float*)d_in[11];
    const float* b_dec1 = (const float*)d_in[12];
    const float* wa1    = (const float*)d_in[13];
    const float* ba1    = (const float*)d_in[14];
    const float* wa2    = (const float*)d_in[15];
    const float* ba2    = (const float*)d_in[16];
    const float* wt1    = (const float*)d_in[17];
    const float* bt1    = (const float*)d_in[18];
    const float* wt2    = (const float*)d_in[19];
    const float* bt2    = (const float*)d_in[20];

    float *xx, *hs0, *cs0, *hs1, *cs1, *score, *hid, *z, *hatt, *tc;
    unsigned *whi, *wlo;
    cudaGetSymbolAddress((void**)&xx, g_xx);
    cudaGetSymbolAddress((void**)&hs0, g_hs0);
    cudaGetSymbolAddress((void**)&cs0, g_cs0);
    cudaGetSymbolAddress((void**)&hs1, g_hs1);
    cudaGetSymbolAddress((void**)&cs1, g_cs1);
    cudaGetSymbolAddress((void**)&score, g_score);
    cudaGetSymbolAddress((void**)&hid, g_hid);
    cudaGetSymbolAddress((void**)&z, g_z);
    cudaGetSymbolAddress((void**)&hatt, g_hatt);
    cudaGetSymbolAddress((void**)&tc, g_tc);
    cudaGetSymbolAddress((void**)&whi, g_whi);
    cudaGetSymbolAddress((void**)&wlo, g_wlo);

    cudaMemcpyAsync(xx, x, sizeof(float) * (size_t)Bn * Tn * Dn * HWp,
                    cudaMemcpyDeviceToDevice);

    // ---- pre-pack mma weights ----
    // enc1/dec0: pack ci 1..64 (base shifted by one channel = +9 floats)
    const int PT = 256;
    wprep<<<(SZ_ENC1  + PT - 1) / PT, PT>>>(w_enc1 + 9, 65, 64, 256, 16, 4, whi + OFF_ENC1,  wlo + OFF_ENC1);
    wprep<<<(SZ_DEC0  + PT - 1) / PT, PT>>>(w_dec0 + 9, 65, 64, 256, 16, 4, whi + OFF_DEC0,  wlo + OFF_DEC0);
    wprep<<<(SZ_WA1   + PT - 1) / PT, PT>>>(wa1,        12, 12, 32,  2, 1,  whi + OFF_WA1,   wlo + OFF_WA1);
    wprep<<<(SZ_WT1HC + PT - 1) / PT, PT>>>(wt1 + 9,   129, 128, 32, 2, 8,  whi + OFF_WT1HC, wlo + OFF_WT1HC);
    wprep<<<(SZ_ENC0  + PT - 1) / PT, PT>>>(w_enc0,     11, 11, 4,   1, 1,  whi + OFF_ENC0,  wlo + OFF_ENC0);
    wprep<<<(SZ_DEC1  + PT - 1) / PT, PT>>>(w_dec1,     65, 64, 4,   1, 4,  whi + OFF_DEC1,  wlo + OFF_DEC1);

    Seg none = mkseg(nullptr, 0, 0, 0, 0);
    const int thr = 256;
    const long HID_RS = (long)Bn * 32 * HWp;

    // ======== encoder layer 0 (hidden 1), compounding input attention ========
    for (int t = 0; t < Tn; t++) {
        const float* hp = (t == 0) ? h0 : hs0 + (long)(t - 1) * HWp;
        long hbs        = (t == 0) ? (long)HWp : (long)Tn * HWp;
        const float* cp = (t == 0) ? c0 : cs0 + (long)(t - 1) * HWp;
        long cbs = hbs;

        mconv(32, 3,
              mkseg(xx, Tn, (long)Dn * HWp, (long)Tn * Dn * HWp, (long)HWp),
              mkseg(hp, 1, 0, hbs, 0),
              mkseg(cp, 1, 0, cbs, 0),
              whi + OFF_WA1, wlo + OFF_WA1, 2, nullptr, 0, nullptr, 0, ba1, 1,
              hid, HID_RS, 32L * HWp, 12, 32, Dn);
        conv(1, 0,
             mkseg(hid, 32, HWp, 32L * HWp, HID_RS), none, none,
             wa2, 32, ba2, nullptr, 0, 0, -1,
             score, (long)HWp, (long)Dn * HWp, 32, 1, Dn);
        inattn_k<<<(Bn * HWp + thr - 1) / thr, thr>>>(score, xx);

        mconv(16, 3,
              mkseg(xx + (long)t * Dn * HWp, Dn, (long)HWp, (long)Tn * Dn * HWp, 0),
              mkseg(hp, 1, 0, hbs, 0), none,
              whi + OFF_ENC0, wlo + OFF_ENC0, 1, nullptr, 0, nullptr, 0, b_enc0, 0,
              z, 0, 4L * HWp, 11, 4, 1);
        long n = (long)Bn * HWp;
        lstm_k<<<(n + thr - 1) / thr, thr>>>(z, cp, cbs,
                                             hs0 + (long)t * HWp, (long)Tn * HWp,
                                             cs0 + (long)t * HWp, (long)Tn * HWp,
                                             nullptr, 0, 1);
    }

    // ======== encoder layer 1 (65->256): MMA over 64 h-ch + exact fp32 aux ch ========
    for (int t = 0; t < Tn; t++) {
        const float* hp = (t == 0) ? h1 : hs1 + (long)(t - 1) * 64 * HWp;
        long hbs        = (t == 0) ? 64L * HWp : (long)Tn * 64 * HWp;
        const float* cp = (t == 0) ? c1 : cs1 + (long)(t - 1) * 64 * HWp;

        mconv(64, 3,
              mkseg(hp, 64, HWp, hbs, 0), none, none,
              whi + OFF_ENC1, wlo + OFF_ENC1, 16,
              hs0 + (long)t * HWp, (long)Tn * HWp, w_enc1, 585,
              b_enc1, 0,
              z, 0, 256L * HWp, 64, 256, 1);
        long n = (long)Bn * 64 * HWp;
        lstm_k<<<(n + thr - 1) / thr, thr>>>(z, cp, hbs,
                                             hs1 + (long)t * 64 * HWp, (long)Tn * 64 * HWp,
                                             cs1 + (long)t * 64 * HWp, (long)Tn * 64 * HWp,
                                             nullptr, 0, 64);
    }

    // ======== temporal-attn h/c conv cache (128->32) all slots: 1-split ========
    mconv(32, 1,
          mkseg(hs1, 64, HWp, (long)Tn * 64 * HWp, 64L * HWp),
          mkseg(cs1, 64, HWp, (long)Tn * 64 * HWp, 64L * HWp), none,
          whi + OFF_WT1HC, wlo + OFF_WT1HC, 2, nullptr, 0, nullptr, 0, bt1, 0,
          tc, HID_RS, 32L * HWp, 128, 32, Tn);

    // ======== decoder ========
    float* out = (float*)d_out;
    for (int s = 0; s < 5; s++) {
        const float* yp; long ybs;
        if (s == 0) { yp = x + 90L * HWp; ybs = 100L * HWp; }
        else        { yp = hs0 + (long)(s - 1) * HWp; ybs = (long)Tn * HWp; }

        conv(8, 1,
             mkseg(yp, 1, 0, ybs, 0), none, none,
             wt1, 129, nullptr, tc, HID_RS, 32L * HWp, s,
             hid, HID_RS, 32L * HWp, 1, 32, Tn);
        conv(1, 0,
             mkseg(hid, 32, HWp, 32L * HWp, HID_RS), none, none,
             wt2, 32, bt2, nullptr, 0, 0, -1,
             score, (long)HWp, (long)Tn * HWp, 32, 1, Tn);
        tattn_k<<<(Bn * HWp + thr - 1) / thr, thr>>>(score, hs1, hatt, s);

        int pl = (s + 9) % Tn;

        // dec0 (65->256): MMA over 64 hatt-ch + exact fp32 aux ch (y)
        mconv(64, 3,
              mkseg(hatt, 64, HWp, 64L * HWp, 0), none, none,
              whi + OFF_DEC0, wlo + OFF_DEC0, 16,
              yp, ybs, w_dec0, 585,
              b_dec0, 0,
              z, 0, 256L * HWp, 64, 256, 1);
        long n64 = (long)Bn * 64 * HWp;
        lstm_k<<<(n64 + thr - 1) / thr, thr>>>(z, cs1 + (long)pl * 64 * HWp, (long)Tn * 64 * HWp,
                                               hs1 + (long)s * 64 * HWp, (long)Tn * 64 * HWp,
                                               cs1 + (long)s * 64 * HWp, (long)Tn * 64 * HWp,
                                               nullptr, 0, 64);

        // refresh tc cache for slot s: 1-split
        mconv(32, 1,
              mkseg(hs1 + (long)s * 64 * HWp, 64, HWp, (long)Tn * 64 * HWp, 0),
              mkseg(cs1 + (long)s * 64 * HWp, 64, HWp, (long)Tn * 64 * HWp, 0), none,
              whi + OFF_WT1HC, wlo + OFF_WT1HC, 2, nullptr, 0, nullptr, 0, bt1, 0,
              tc + (long)s * HID_RS, 0, 32L * HWp, 128, 32, 1);

        // dec1 (65->4): MMA over 64 hs1-ch + exact fp32 aux ch (hs0 last)
        mconv(16, 3,
              mkseg(hs1 + (long)s * 64 * HWp, 64, HWp, (long)Tn * 64 * HWp, 0), none, none,
              whi + OFF_DEC1, wlo + OFF_DEC1, 1,
              hs0 + (long)pl * HWp, (long)Tn * HWp, w_dec1 + 64 * 9, 585,
              b_dec1, 0,
              z, 0, 4L * HWp, 64, 4, 1);
        long n1 = (long)Bn * HWp;
        lstm_k<<<(n1 + thr - 1) / thr, thr>>>(z, cs0 + (long)pl * HWp, (long)Tn * HWp,
                                              hs0 + (long)s * HWp, (long)Tn * HWp,
                                              cs0 + (long)s * HWp, (long)Tn * HWp,
                                              out + (long)s * HWp, 5L * HWp, 1);
    }
}

// round 14
// speedup vs baseline: 1.4369x; 1.2536x over previous
#include <cuda_runtime.h>
#include <cuda_bf16.h>
#include <math.h>

#define HWp 16384
#define Hdim 128
#define Wdim 128
#define Bn 8
#define Tn 10
#define Dn 10

// ---------------- scratch state (device globals) ----------------
__device__ float g_xx[(size_t)Bn*Tn*Dn*HWp];
__device__ float g_hs0[(size_t)Bn*Tn*HWp];
__device__ float g_cs0[(size_t)Bn*Tn*HWp];
__device__ float g_hs1[(size_t)Bn*Tn*64*HWp];
__device__ float g_cs1[(size_t)Bn*Tn*64*HWp];
__device__ float g_score[(size_t)Bn*Tn*HWp];
__device__ float g_hid[(size_t)Tn*Bn*32*HWp];
__device__ float g_z[(size_t)Bn*256*HWp];
__device__ float g_hatt[(size_t)Bn*64*HWp];
__device__ float g_tc[(size_t)Tn*Bn*32*HWp];

// pre-packed fragment-order bf16x2 weights (hi/lo)
#define WTOT 173952
__device__ __align__(16) unsigned g_whi[WTOT];
__device__ __align__(16) unsigned g_wlo[WTOT];
// layout [(cb*9+tap)*MTall + mtile]*128 + lane*4 + j
#define OFF_ENC1  0
#define SZ_ENC1   73728      // nCh=4 (ci 1..64), MTall=16
#define OFF_DEC0  73728
#define SZ_DEC0   73728      // nCh=4 (ci 1..64), MTall=16
#define OFF_WA1   147456
#define SZ_WA1    2304       // nCh=1, MTall=2
#define OFF_WT1HC 149760
#define SZ_WT1HC  18432      // nCh=8, MTall=2
#define OFF_ENC0  168192
#define SZ_ENC0   1152       // nCh=1, MTall=1
#define OFF_DEC1  169344
#define SZ_DEC1   4608       // nCh=4 (ci 0..63), MTall=1

__device__ __forceinline__ float sigm(float x) { return 1.f / (1.f + __expf(-x)); }

__device__ __forceinline__ unsigned packbf(__nv_bfloat16 a, __nv_bfloat16 b) {
    return ((unsigned)__bfloat16_as_ushort(b) << 16) | __bfloat16_as_ushort(a);
}
__device__ __forceinline__ void splitbf(float v, __nv_bfloat16& h, __nv_bfloat16& l) {
    h = __float2bfloat16(v);
    l = __float2bfloat16(v - __bfloat162float(h));
}
__device__ __forceinline__ void mma16(float* c, const unsigned* a, const unsigned* b) {
    asm volatile("mma.sync.aligned.m16n8k16.row.col.f32.bf16.bf16.f32 "
        "{%0,%1,%2,%3}, {%4,%5,%6,%7}, {%8,%9}, {%0,%1,%2,%3};"
        : "+f"(c[0]), "+f"(c[1]), "+f"(c[2]), "+f"(c[3])
        : "r"(a[0]), "r"(a[1]), "r"(a[2]), "r"(a[3]), "r"(b[0]), "r"(b[1]));
}

// ---------------- weight pre-pack into m16n8k16 fragment order ----------------
__global__ void wprep(const float* __restrict__ wgt, int Cw, int Cin, int Cout,
                      int MTall, int nCh, unsigned* __restrict__ whi,
                      unsigned* __restrict__ wlo)
{
    int idx = blockIdx.x * blockDim.x + threadIdx.x;
    int total = nCh * 9 * MTall * 128;
    if (idx >= total) return;
    int li = idx & 127;
    int j = li & 3, ln = li >> 2;
    int f = idx >> 7;
    int mtile = f % MTall;
    int tap = (f / MTall) % 9;
    int cb = f / (MTall * 9);
    int g = ln >> 2, q = ln & 3;
    int co = mtile * 16 + g + (j & 1) * 8;
    int kb = 2 * q + (j >> 1) * 8;
    int ci0 = cb * 16 + kb;
    float w0 = 0.f, w1 = 0.f;
    if (co < Cout) {
        if (ci0 < Cin)     w0 = wgt[((long)co * Cw + ci0) * 9 + tap];
        if (ci0 + 1 < Cin) w1 = wgt[((long)co * Cw + ci0 + 1) * 9 + tap];
    }
    __nv_bfloat16 h0, l0, h1, l1;
    splitbf(w0, h0, l0);
    splitbf(w1, h1, l1);
    whi[idx] = packbf(h0, h1);
    wlo[idx] = packbf(l0, l1);
}

// =============== implicit-GEMM 3x3 conv, bf16 hi/lo split, m16n8k16 ===============
// SPLIT=3: hi/lo split (~fp32); SPLIT=1: plain bf16.
// Split phases ordered OUTERMOST per tap so consecutive MMAs hit different
// accumulators (RAW distance = NT*MT instead of 1). 2 CTAs/SM via launch bounds.
// Optional aux channel convolved exactly in fp32 in the epilogue.
template <int MBLK, int WN, int SPLIT>
__global__ void __launch_bounds__(256, 2) mmaconv(
    const float* __restrict__ in0, int n0, long c0s, long b0s, long r0s,
    const float* __restrict__ in1, int n1, long c1s, long b1s, long r1s,
    const float* __restrict__ in2, int n2, long c2s, long b2s, long r2s,
    const unsigned* __restrict__ whi, const unsigned* __restrict__ wlo, int MTall,
    const float* __restrict__ aux, long aux_bs,
    const float* __restrict__ wax, int wstr,
    const float* __restrict__ bias, int act,
    float* __restrict__ out, long o_rs, long obs, int Cin, int Cout)
{
    constexpr int WM = 8 / WN;
    constexpr int MT = MBLK / (16 * WM);
    constexpr int NT = 32 / WN;

    __shared__ unsigned in_hi[2][8 * 360];
    __shared__ unsigned in_lo[(SPLIT == 3) ? 2 : 1][(SPLIT == 3) ? 8 * 360 : 1];
    __shared__ float auxs[18 * 19];

    int b = blockIdx.z % Bn;
    int r = blockIdx.z / Bn;
    int cobase = blockIdx.y * MBLK;
    int ty0 = (blockIdx.x >> 3) * 16, tx0 = (blockIdx.x & 7) * 16;

    int tid = threadIdx.x;
    int wid = tid >> 5, lane = tid & 31;
    int g = lane >> 2, q = lane & 3;
    int cowb = (wid / WN) * (MT * 16);
    int pwb  = (wid % WN) * (NT * 8);

    int pixoff[NT];
#pragma unroll
    for (int nt = 0; nt < NT; nt++) {
        int px = pwb + nt * 8 + g;
        pixoff[nt] = (px >> 4) * 19 + (px & 15);
    }

    float acc[MT][NT][4];
#pragma unroll
    for (int mt = 0; mt < MT; mt++)
#pragma unroll
        for (int nt = 0; nt < NT; nt++)
#pragma unroll
            for (int i = 0; i < 4; i++) acc[mt][nt][i] = 0.f;

    // stage aux channel halo tile (fp32)
    if (aux) {
        for (int i = tid; i < 324; i += 256) {
            int rr = i / 18, cc = i - rr * 18;
            int gy = ty0 + rr - 1, gx = tx0 + cc - 1;
            float v = 0.f;
            if (gy >= 0 && gy < Hdim && gx >= 0 && gx < Wdim)
                v = aux[(long)b * aux_bs + gy * Wdim + gx];
            auxs[rr * 19 + cc] = v;
        }
    }

    auto ldci = [&](int cig, int go) -> float {
        if (cig >= Cin) return 0.f;
        const float* src;
        if (cig < n0)           src = in0 + (long)b * b0s + (long)r * r0s + (long)cig * c0s;
        else if (cig < n0 + n1) src = in1 + (long)b * b1s + (long)r * r1s + (long)(cig - n0) * c1s;
        else                    src = in2 + (long)b * b2s + (long)r * r2s + (long)(cig - n0 - n1) * c2s;
        return src[go];
    };
    auto stage = [&](int cb, int buf) {
#pragma unroll
        for (int jj = 0; jj < 11; jj++) {
            int i = tid + jj * 256;
            if (i >= 2592) continue;
            int cp = i / 324; int rem = i - cp * 324;
            int rr = rem / 18, cc = rem - rr * 18;
            int gy = ty0 + rr - 1, gx = tx0 + cc - 1;
            float v0 = 0.f, v1 = 0.f;
            if (gy >= 0 && gy < Hdim && gx >= 0 && gx < Wdim) {
                int go = gy * Wdim + gx;
                int ci0 = cb * 16 + 2 * cp;
                v0 = ldci(ci0, go);
                v1 = ldci(ci0 + 1, go);
            }
            __nv_bfloat16 h0, l0, h1, l1;
            splitbf(v0, h0, l0);
            splitbf(v1, h1, l1);
            int so = cp * 360 + rr * 19 + cc;
            in_hi[buf][so] = packbf(h0, h1);
            if (SPLIT == 3) in_lo[buf][so] = packbf(l0, l1);
        }
    };

    int nCh = (Cin + 15) >> 4;
    stage(0, 0);
    __syncthreads();

    for (int cb = 0; cb < nCh; cb++) {
        int buf = cb & 1;
        if (cb + 1 < nCh) stage(cb + 1, buf ^ 1);

        long wchunk = (long)cb * 9 * MTall * 128;
#pragma unroll
        for (int tap = 0; tap < 9; tap++) {
            int toff = (tap / 3) * 19 + (tap % 3);
            const unsigned* bh0 = &in_hi[buf][q * 360 + toff];
            const unsigned* bh1 = &in_hi[buf][(q + 4) * 360 + toff];
            const unsigned* bl0 = &in_lo[(SPLIT == 3) ? buf : 0][(SPLIT == 3) ? q * 360 + toff : 0];
            const unsigned* bl1 = &in_lo[(SPLIT == 3) ? buf : 0][(SPLIT == 3) ? (q + 4) * 360 + toff : 0];
#pragma unroll
            for (int ph = 0; ph < SPLIT; ph++) {
                // phase 0: ahi*bhi, phase 1: ahi*blo, phase 2: alo*bhi
                uint4 afr[MT];
#pragma unroll
                for (int mt = 0; mt < MT; mt++) {
                    int mtg = (cobase >> 4) + (cowb >> 4) + mt;
                    long fb = wchunk + ((long)tap * MTall + mtg) * 128 + lane * 4;
                    afr[mt] = (ph == 2) ? *(const uint4*)&wlo[fb]
                                        : *(const uint4*)&whi[fb];
                }
#pragma unroll
                for (int nt = 0; nt < NT; nt++) {
                    unsigned bb[2];
                    if (ph == 1) { bb[0] = bl0[pixoff[nt]]; bb[1] = bl1[pixoff[nt]]; }
                    else         { bb[0] = bh0[pixoff[nt]]; bb[1] = bh1[pixoff[nt]]; }
#pragma unroll
                    for (int mt = 0; mt < MT; mt++)
                        mma16(acc[mt][nt], (const unsigned*)&afr[mt], bb);
                }
            }
        }
        __syncthreads();
    }

    // ---- epilogue (+ exact fp32 aux-channel conv) ----
#pragma unroll
    for (int mt = 0; mt < MT; mt++) {
#pragma unroll
        for (int half = 0; half < 2; half++) {
            int co = cobase + cowb + mt * 16 + g + half * 8;
            if (co >= Cout) continue;
            float bs = bias ? bias[co] : 0.f;
            float w9[9];
            if (aux) {
#pragma unroll
                for (int t9 = 0; t9 < 9; t9++) w9[t9] = wax[(long)co * wstr + t9];
            }
            float* op = out + (long)r * o_rs + (long)b * obs + (long)co * HWp;
#pragma unroll
            for (int nt = 0; nt < NT; nt++) {
                int px = pwb + nt * 8 + 2 * q;
                int pr = px >> 4, pc = px & 15;
                int gp = (ty0 + pr) * Wdim + tx0 + pc;
                float v0 = acc[mt][nt][half * 2] + bs;
                float v1 = acc[mt][nt][half * 2 + 1] + bs;
                if (aux) {
#pragma unroll
                    for (int dy = 0; dy < 3; dy++)
#pragma unroll
                        for (int dx = 0; dx < 3; dx++) {
                            float w = w9[dy * 3 + dx];
                            v0 = fmaf(w, auxs[(pr + dy) * 19 + pc + dx], v0);
                            v1 = fmaf(w, auxs[(pr + dy) * 19 + pc + 1 + dx], v1);
                        }
                }
                if (act) { v0 = tanhf(v0); v1 = tanhf(v1); }
                op[gp] = v0; op[gp + 1] = v1;
            }
        }
    }
}

// =============== FFMA fallback conv (small Cout paths) ===============
template <int CB, int ACT>
__global__ void __launch_bounds__(256) convk(
    const float* __restrict__ in0, int n0, long c0s, long b0s, long r0s,
    const float* __restrict__ in1, int n1, long c1s, long b1s, long r1s,
    const float* __restrict__ in2, int n2, long c2s, long b2s, long r2s,
    const float* __restrict__ wgt, int Cw,
    const float* __restrict__ bias,
    const float* __restrict__ radd, long radd_rs, long radd_bs, int ring_s,
    float* __restrict__ out, long o_rs, long obs,
    int Cin, int Cout, int nCo)
{
    __shared__ float tile[2][34 * 34];
    __shared__ float wsm[2][CB][9];

    int z = blockIdx.z;
    int cb = z % nCo;
    int zb = z / nCo;
    int b = zb % Bn;
    int r = zb / Bn;
    int cobase = cb * CB;

    int tid = threadIdx.x;
    int txc = tid & 15, tyr = tid >> 4;
    int x0 = blockIdx.x * 32, y0 = blockIdx.y * 32;

    int goff[5]; bool gok[5];
#pragma unroll
    for (int j = 0; j < 5; j++) {
        int i = tid + j * 256;
        int rr = i / 34, cc = i - rr * 34;
        int gy = y0 + rr - 1, gx = x0 + cc - 1;
        gok[j] = (i < 34 * 34) && (gy >= 0) && (gy < Hdim) && (gx >= 0) && (gx < Wdim);
        goff[j] = gy * Wdim + gx;
    }
    bool wldr = tid < CB * 9;
    int wco = tid / 9, wk = tid - wco * 9;
    bool wok = wldr && (cobase + wco < Cout);
    long wbase = ((long)(cobase + wco) * Cw) * 9 + wk;

    float acc[CB][4];
#pragma unroll
    for (int co = 0; co < CB; co++)
#pragma unroll
        for (int qq = 0; qq < 4; qq++) acc[co][qq] = 0.f;

    auto load_cin = [&](int cin, int p) {
        const float* src;
        if (cin < n0)           src = in0 + (long)b * b0s + (long)r * r0s + (long)cin * c0s;
        else if (cin < n0 + n1) src = in1 + (long)b * b1s + (long)r * r1s + (long)(cin - n0) * c1s;
        else                    src = in2 + (long)b * b2s + (long)r * r2s + (long)(cin - n0 - n1) * c2s;
#pragma unroll
        for (int j = 0; j < 4; j++)
            tile[p][tid + j * 256] = gok[j] ? src[goff[j]] : 0.f;
        if (tid + 1024 < 34 * 34)
            tile[p][tid + 1024] = gok[4] ? src[goff[4]] : 0.f;
        if (wldr)
            wsm[p][wco][wk] = wok ? wgt[wbase + (long)cin * 9] : 0.f;
    };

    load_cin(0, 0);
    __syncthreads();

    for (int cin = 0; cin < Cin; cin++) {
        int p = cin & 1;
        if (cin + 1 < Cin) load_cin(cin + 1, p ^ 1);

        float v[4][4];
#pragma unroll
        for (int rr = 0; rr < 4; rr++)
#pragma unroll
            for (int cc = 0; cc < 4; cc++)
                v[rr][cc] = tile[p][(2 * tyr + rr) * 34 + 2 * txc + cc];

#pragma unroll
        for (int co = 0; co < CB; co++) {
#pragma unroll
            for (int k = 0; k < 9; k++) {
                float w = wsm[p][co][k];
                int dy = k / 3, dx = k % 3;
                acc[co][0] = fmaf(v[dy][dx],         w, acc[co][0]);
                acc[co][1] = fmaf(v[dy][dx + 1],     w, acc[co][1]);
                acc[co][2] = fmaf(v[dy + 1][dx],     w, acc[co][2]);
                acc[co][3] = fmaf(v[dy + 1][dx + 1], w, acc[co][3]);
            }
        }
        __syncthreads();
    }

    int ox = x0 + 2 * txc, oy = y0 + 2 * tyr;
    long p0 = (long)oy * Wdim + ox;
    int pr = (radd && ring_s >= 0) ? (ring_s + r) % Tn : r;
#pragma unroll
    for (int co = 0; co < CB; co++) {
        int c = cobase + co;
        if (c >= Cout) continue;
        float bs = bias ? bias[c] : 0.f;
        float v0 = acc[co][0] + bs, v1 = acc[co][1] + bs;
        float v2 = acc[co][2] + bs, v3 = acc[co][3] + bs;
        if (radd) {
            const float* ra = radd + (long)pr * radd_rs + (long)b * radd_bs + (long)c * HWp + p0;
            v0 += ra[0]; v1 += ra[1]; v2 += ra[Wdim]; v3 += ra[Wdim + 1];
        }
        if (ACT == 1) { v0 = tanhf(v0); v1 = tanhf(v1); v2 = tanhf(v2); v3 = tanhf(v3); }
        float* o = out + (long)r * o_rs + (long)b * obs + (long)c * HWp + p0;
        o[0] = v0; o[1] = v1; o[Wdim] = v2; o[Wdim + 1] = v3;
    }
}

// ---------------- LSTM pointwise gate update ----------------
__global__ void lstm_k(const float* __restrict__ z, const float* __restrict__ cin, long cin_bs,
                       float* __restrict__ hout, long h_bs, float* __restrict__ cout_, long c_bs,
                       float* __restrict__ hout2, long h2_bs, int C)
{
    long total = (long)Bn * C * HWp;
    long idx = (long)blockIdx.x * blockDim.x + threadIdx.x;
    if (idx >= total) return;
    long CHW = (long)C * HWp;
    int b = (int)(idx / CHW);
    long r = idx - (long)b * CHW;
    const float* zb = z + (long)b * 4 * CHW;
    float zi = zb[r], zf = zb[CHW + r], zo = zb[2 * CHW + r], zg = zb[3 * CHW + r];
    float c = cin[(long)b * cin_bs + r];
    float c2 = sigm(zf) * c + sigm(zi) * tanhf(zg);
    float h2 = sigm(zo) * tanhf(c2);
    hout[(long)b * h_bs + r] = h2;
    cout_[(long)b * c_bs + r] = c2;
    if (hout2) hout2[(long)b * h2_bs + r] = h2;
}

// ---------------- input attention softmax + compounding reweight ----------------
__global__ void inattn_k(const float* __restrict__ score, float* __restrict__ xx)
{
    int idx = blockIdx.x * blockDim.x + threadIdx.x;
    if (idx >= Bn * HWp) return;
    int b = idx / HWp, p = idx - b * HWp;
    const float* sc = score + (long)b * Dn * HWp + p;
    float s[Dn];
    float m = -1e30f;
#pragma unroll
    for (int k = 0; k < Dn; k++) { s[k] = sc[(long)k * HWp]; m = fmaxf(m, s[k]); }
    float sum = 0.f;
#pragma unroll
    for (int k = 0; k < Dn; k++) { s[k] = __expf(s[k] - m); sum += s[k]; }
    float inv = 1.f / sum;
    float* xb = xx + (long)b * Tn * Dn * HWp + p;
#pragma unroll
    for (int k = 0; k < Dn; k++) {
        float a = s[k] * inv;
        for (int t = 0; t < Tn; t++) xb[((long)t * Dn + k) * HWp] *= a;
    }
}

// ---------------- temporal attention softmax + weighted sum ----------------
__global__ void tattn_k(const float* __restrict__ score, const float* __restrict__ hs1,
                        float* __restrict__ hatt, int s)
{
    int idx = blockIdx.x * blockDim.x + threadIdx.x;
    if (idx >= Bn * HWp) return;
    int b = idx / HWp, p = idx - b * HWp;
    const float* sc = score + (long)b * Tn * HWp + p;
    float bt[Tn];
    float m = -1e30f;
#pragma unroll
    for (int t = 0; t < Tn; t++) { bt[t] = sc[(long)t * HWp]; m = fmaxf(m, bt[t]); }
    float sum = 0.f;
#pragma unroll
    for (int t = 0; t < Tn; t++) { bt[t] = __expf(bt[t] - m); sum += bt[t]; }
    float inv = 1.f / sum;
    float acc[64];
#pragma unroll
    for (int c = 0; c < 64; c++) acc[c] = 0.f;
    for (int t = 0; t < Tn; t++) {
        int phys = (s + t) % Tn;
        const float* hb = hs1 + ((long)b * Tn + phys) * 64 * HWp + p;
        float w = bt[t] * inv;
#pragma unroll
        for (int c = 0; c < 64; c++) acc[c] = fmaf(hb[(long)c * HWp], w, acc[c]);
    }
    float* ob = hatt + (long)b * 64 * HWp + p;
#pragma unroll
    for (int c = 0; c < 64; c++) ob[(long)c * HWp] = acc[c];
}

// ---------------- host side ----------------
struct Seg { const float* p; int n; long cs, bs, rs; };
static inline Seg mkseg(const float* p, int n, long cs, long bs, long rs) {
    Seg s; s.p = p; s.n = n; s.cs = cs; s.bs = bs; s.rs = rs; return s;
}

static void conv(int CB, int ACT, Seg a, Seg b, Seg c,
                 const float* w, int Cw, const float* bias,
                 const float* radd, long rrs, long rbs, int ring_s,
                 float* out, long ors, long obs, int Cin, int Cout, int R)
{
    int nCo = (Cout + CB - 1) / CB;
    dim3 grid(Wdim / 32, Hdim / 32, R * Bn * nCo);
#define CARGS a.p, a.n, a.cs, a.bs, a.rs, b.p, b.n, b.cs, b.bs, b.rs, c.p, c.n, c.cs, c.bs, c.rs, \
              w, Cw, bias, radd, rrs, rbs, ring_s, out, ors, obs, Cin, Cout, nCo
    if (CB == 8 && ACT == 1) convk<8, 1><<<grid, 256>>>(CARGS);
    else if (CB == 8)        convk<8, 0><<<grid, 256>>>(CARGS);
    else                     convk<1, 0><<<grid, 256>>>(CARGS);
#undef CARGS
}

static void mconv(int MBLK, int SPLIT, Seg a, Seg b, Seg c,
                  const unsigned* whi, const unsigned* wlo, int MTall,
                  const float* aux, long aux_bs, const float* wax, int wstr,
                  const float* bias, int act,
                  float* out, long ors, long obs, int Cin, int Cout, int R)
{
    dim3 grid(64, (Cout + MBLK - 1) / MBLK, R * Bn);
#define MARGS a.p, a.n, a.cs, a.bs, a.rs, b.p, b.n, b.cs, b.bs, b.rs, c.p, c.n, c.cs, c.bs, c.rs, \
              whi, wlo, MTall, aux, aux_bs, wax, wstr, bias, act, out, ors, obs, Cin, Cout
    if (MBLK == 64)                     mmaconv<64, 4, 3><<<grid, 256>>>(MARGS);
    else if (MBLK == 32 && SPLIT == 1)  mmaconv<32, 8, 1><<<grid, 256>>>(MARGS);
    else if (MBLK == 32)                mmaconv<32, 8, 3><<<grid, 256>>>(MARGS);
    else                                mmaconv<16, 8, 3><<<grid, 256>>>(MARGS);
#undef MARGS
}

extern "C" void kernel_launch(void* const* d_in, const int* in_sizes, int n_in,
                              void* d_out, int out_size)
{
    const float* x      = (const float*)d_in[0];
    const float* h0     = (const float*)d_in[1];
    const float* c0     = (const float*)d_in[2];
    const float* h1     = (const float*)d_in[3];
    const float* c1     = (const float*)d_in[4];
    const float* w_enc0 = (const float*)d_in[5];
    const float* b_enc0 = (const float*)d_in[6];
    const float* w_enc1 = (const float*)d_in[7];
    const float* b_enc1 = (const float*)d_in[8];
    const float* w_dec0 = (const float*)d_in[9];
    const float* b_dec0 = (const float*)d_in[10];
    const float* w_dec1 = (const float*)d_in[11];
    const float* b_dec1 = (const float*)d_in[12];
    const float* wa1    = (const float*)d_in[13];
    const float* ba1    = (const float*)d_in[14];
    const float* wa2    = (const float*)d_in[15];
    const float* ba2    = (const float*)d_in[16];
    const float* wt1    = (const float*)d_in[17];
    const float* bt1    = (const float*)d_in[18];
    const float* wt2    = (const float*)d_in[19];
    const float* bt2    = (const float*)d_in[20];

    float *xx, *hs0, *cs0, *hs1, *cs1, *score, *hid, *z, *hatt, *tc;
    unsigned *whi, *wlo;
    cudaGetSymbolAddress((void**)&xx, g_xx);
    cudaGetSymbolAddress((void**)&hs0, g_hs0);
    cudaGetSymbolAddress((void**)&cs0, g_cs0);
    cudaGetSymbolAddress((void**)&hs1, g_hs1);
    cudaGetSymbolAddress((void**)&cs1, g_cs1);
    cudaGetSymbolAddress((void**)&score, g_score);
    cudaGetSymbolAddress((void**)&hid, g_hid);
    cudaGetSymbolAddress((void**)&z, g_z);
    cudaGetSymbolAddress((void**)&hatt, g_hatt);
    cudaGetSymbolAddress((void**)&tc, g_tc);
    cudaGetSymbolAddress((void**)&whi, g_whi);
    cudaGetSymbolAddress((void**)&wlo, g_wlo);

    cudaMemcpyAsync(xx, x, sizeof(float) * (size_t)Bn * Tn * Dn * HWp,
                    cudaMemcpyDeviceToDevice);

    // ---- pre-pack mma weights ----
    const int PT = 256;
    wprep<<<(SZ_ENC1  + PT - 1) / PT, PT>>>(w_enc1 + 9, 65, 64, 256, 16, 4, whi + OFF_ENC1,  wlo + OFF_ENC1);
    wprep<<<(SZ_DEC0  + PT - 1) / PT, PT>>>(w_dec0 + 9, 65, 64, 256, 16, 4, whi + OFF_DEC0,  wlo + OFF_DEC0);
    wprep<<<(SZ_WA1   + PT - 1) / PT, PT>>>(wa1,        12, 12, 32,  2, 1,  whi + OFF_WA1,   wlo + OFF_WA1);
    wprep<<<(SZ_WT1HC + PT - 1) / PT, PT>>>(wt1 + 9,   129, 128, 32, 2, 8,  whi + OFF_WT1HC, wlo + OFF_WT1HC);
    wprep<<<(SZ_ENC0  + PT - 1) / PT, PT>>>(w_enc0,     11, 11, 4,   1, 1,  whi + OFF_ENC0,  wlo + OFF_ENC0);
    wprep<<<(SZ_DEC1  + PT - 1) / PT, PT>>>(w_dec1,     65, 64, 4,   1, 4,  whi + OFF_DEC1,  wlo + OFF_DEC1);

    Seg none = mkseg(nullptr, 0, 0, 0, 0);
    const int thr = 256;
    const long HID_RS = (long)Bn * 32 * HWp;

    // ======== encoder layer 0 (hidden 1), compounding input attention ========
    for (int t = 0; t < Tn; t++) {
        const float* hp = (t == 0) ? h0 : hs0 + (long)(t - 1) * HWp;
        long hbs        = (t == 0) ? (long)HWp : (long)Tn * HWp;
        const float* cp = (t == 0) ? c0 : cs0 + (long)(t - 1) * HWp;
        long cbs = hbs;

        mconv(32, 3,
              mkseg(xx, Tn, (long)Dn * HWp, (long)Tn * Dn * HWp, (long)HWp),
              mkseg(hp, 1, 0, hbs, 0),
              mkseg(cp, 1, 0, cbs, 0),
              whi + OFF_WA1, wlo + OFF_WA1, 2, nullptr, 0, nullptr, 0, ba1, 1,
              hid, HID_RS, 32L * HWp, 12, 32, Dn);
        conv(1, 0,
             mkseg(hid, 32, HWp, 32L * HWp, HID_RS), none, none,
             wa2, 32, ba2, nullptr, 0, 0, -1,
             score, (long)HWp, (long)Dn * HWp, 32, 1, Dn);
        inattn_k<<<(Bn * HWp + thr - 1) / thr, thr>>>(score, xx);

        mconv(16, 3,
              mkseg(xx + (long)t * Dn * HWp, Dn, (long)HWp, (long)Tn * Dn * HWp, 0),
              mkseg(hp, 1, 0, hbs, 0), none,
              whi + OFF_ENC0, wlo + OFF_ENC0, 1, nullptr, 0, nullptr, 0, b_enc0, 0,
              z, 0, 4L * HWp, 11, 4, 1);
        long n = (long)Bn * HWp;
        lstm_k<<<(n + thr - 1) / thr, thr>>>(z, cp, cbs,
                                             hs0 + (long)t * HWp, (long)Tn * HWp,
                                             cs0 + (long)t * HWp, (long)Tn * HWp,
                                             nullptr, 0, 1);
    }

    // ======== encoder layer 1 (65->256): MMA over 64 h-ch + exact fp32 aux ch ========
    for (int t = 0; t < Tn; t++) {
        const float* hp = (t == 0) ? h1 : hs1 + (long)(t - 1) * 64 * HWp;
        long hbs        = (t == 0) ? 64L * HWp : (long)Tn * 64 * HWp;
        const float* cp = (t == 0) ? c1 : cs1 + (long)(t - 1) * 64 * HWp;

        mconv(64, 3,
              mkseg(hp, 64, HWp, hbs, 0), none, none,
              whi + OFF_ENC1, wlo + OFF_ENC1, 16,
              hs0 + (long)t * HWp, (long)Tn * HWp, w_enc1, 585,
              b_enc1, 0,
              z, 0, 256L * HWp, 64, 256, 1);
        long n = (long)Bn * 64 * HWp;
        lstm_k<<<(n + thr - 1) / thr, thr>>>(z, cp, hbs,
                                             hs1 + (long)t * 64 * HWp, (long)Tn * 64 * HWp,
                                             cs1 + (long)t * 64 * HWp, (long)Tn * 64 * HWp,
                                             nullptr, 0, 64);
    }

    // ======== temporal-attn h/c conv cache (128->32) all slots: 1-split ========
    mconv(32, 1,
          mkseg(hs1, 64, HWp, (long)Tn * 64 * HWp, 64L * HWp),
          mkseg(cs1, 64, HWp, (long)Tn * 64 * HWp, 64L * HWp), none,
          whi + OFF_WT1HC, wlo + OFF_WT1HC, 2, nullptr, 0, nullptr, 0, bt1, 0,
          tc, HID_RS, 32L * HWp, 128, 32, Tn);

    // ======== decoder ========
    float* out = (float*)d_out;
    for (int s = 0; s < 5; s++) {
        const float* yp; long ybs;
        if (s == 0) { yp = x + 90L * HWp; ybs = 100L * HWp; }
        else        { yp = hs0 + (long)(s - 1) * HWp; ybs = (long)Tn * HWp; }

        conv(8, 1,
             mkseg(yp, 1, 0, ybs, 0), none, none,
             wt1, 129, nullptr, tc, HID_RS, 32L * HWp, s,
             hid, HID_RS, 32L * HWp, 1, 32, Tn);
        conv(1, 0,
             mkseg(hid, 32, HWp, 32L * HWp, HID_RS), none, none,
             wt2, 32, bt2, nullptr, 0, 0, -1,
             score, (long)HWp, (long)Tn * HWp, 32, 1, Tn);
        tattn_k<<<(Bn * HWp + thr - 1) / thr, thr>>>(score, hs1, hatt, s);

        int pl = (s + 9) % Tn;

        // dec0 (65->256): MMA over 64 hatt-ch + exact fp32 aux ch (y)
        mconv(64, 3,
              mkseg(hatt, 64, HWp, 64L * HWp, 0), none, none,
              whi + OFF_DEC0, wlo + OFF_DEC0, 16,
              yp, ybs, w_dec0, 585,
              b_dec0, 0,
              z, 0, 256L * HWp, 64, 256, 1);
        long n64 = (long)Bn * 64 * HWp;
        lstm_k<<<(n64 + thr - 1) / thr, thr>>>(z, cs1 + (long)pl * 64 * HWp, (long)Tn * 64 * HWp,
                                               hs1 + (long)s * 64 * HWp, (long)Tn * 64 * HWp,
                                               cs1 + (long)s * 64 * HWp, (long)Tn * 64 * HWp,
                                               nullptr, 0, 64);

        // refresh tc cache for slot s: 1-split
        mconv(32, 1,
              mkseg(hs1 + (long)s * 64 * HWp, 64, HWp, (long)Tn * 64 * HWp, 0),
              mkseg(cs1 + (long)s * 64 * HWp, 64, HWp, (long)Tn * 64 * HWp, 0), none,
              whi + OFF_WT1HC, wlo + OFF_WT1HC, 2, nullptr, 0, nullptr, 0, bt1, 0,
              tc + (long)s * HID_RS, 0, 32L * HWp, 128, 32, 1);

        // dec1 (65->4): MMA over 64 hs1-ch + exact fp32 aux ch (hs0 last)
        mconv(16, 3,
              mkseg(hs1 + (long)s * 64 * HWp, 64, HWp, (long)Tn * 64 * HWp, 0), none, none,
              whi + OFF_DEC1, wlo + OFF_DEC1, 1,
              hs0 + (long)pl * HWp, (long)Tn * HWp, w_dec1 + 64 * 9, 585,
              b_dec1, 0,
              z, 0, 4L * HWp, 64, 4, 1);
        long n1 = (long)Bn * HWp;
        lstm_k<<<(n1 + thr - 1) / thr, thr>>>(z, cs0 + (long)pl * HWp, (long)Tn * HWp,
                                              hs0 + (long)s * HWp, (long)Tn * HWp,
                                              cs0 + (long)s * HWp, (long)Tn * HWp,
                                              out + (long)s * HWp, 5L * HWp, 1);
    }
}

// round 15
// speedup vs baseline: 1.4443x; 1.0052x over previous
#include <cuda_runtime.h>
#include <cuda_bf16.h>
#include <math.h>

#define HWp 16384
#define Hdim 128
#define Wdim 128
#define Bn 8
#define Tn 10
#define Dn 10

// ---------------- scratch state (device globals) ----------------
__device__ float g_xx[(size_t)Bn*Tn*Dn*HWp];
__device__ float g_hs0[(size_t)Bn*Tn*HWp];
__device__ float g_cs0[(size_t)Bn*Tn*HWp];
__device__ float g_hs1[(size_t)Bn*Tn*64*HWp];
__device__ float g_cs1[(size_t)Bn*Tn*64*HWp];
__device__ float g_score[(size_t)Bn*Tn*HWp];
__device__ float g_hid[(size_t)Tn*Bn*32*HWp];
__device__ float g_z[(size_t)Bn*256*HWp];
__device__ float g_hatt[(size_t)Bn*64*HWp];
__device__ float g_tc[(size_t)Tn*Bn*32*HWp];

// pre-packed fragment-order bf16x2 weights (hi/lo)
#define WTOT 173952
__device__ __align__(16) unsigned g_whi[WTOT];
__device__ __align__(16) unsigned g_wlo[WTOT];
// layout [(cb*9+tap)*MTall + mtile]*128 + lane*4 + j
#define OFF_ENC1  0
#define SZ_ENC1   73728      // nCh=4 (ci 1..64), MTall=16, gate-interleaved
#define OFF_DEC0  73728
#define SZ_DEC0   73728
#define OFF_WA1   147456
#define SZ_WA1    2304       // nCh=1, MTall=2
#define OFF_WT1HC 149760
#define SZ_WT1HC  18432      // nCh=8, MTall=2
#define OFF_ENC0  168192
#define SZ_ENC0   1152       // nCh=1, MTall=1
#define OFF_DEC1  169344
#define SZ_DEC1   4608       // nCh=4 (ci 0..63), MTall=1

__device__ __forceinline__ float sigm(float x) { return 1.f / (1.f + __expf(-x)); }

__device__ __forceinline__ unsigned packbf(__nv_bfloat16 a, __nv_bfloat16 b) {
    return ((unsigned)__bfloat16_as_ushort(b) << 16) | __bfloat16_as_ushort(a);
}
__device__ __forceinline__ void splitbf(float v, __nv_bfloat16& h, __nv_bfloat16& l) {
    h = __float2bfloat16(v);
    l = __float2bfloat16(v - __bfloat162float(h));
}
__device__ __forceinline__ void mma16(float* c, const unsigned* a, const unsigned* b) {
    asm volatile("mma.sync.aligned.m16n8k16.row.col.f32.bf16.bf16.f32 "
        "{%0,%1,%2,%3}, {%4,%5,%6,%7}, {%8,%9}, {%0,%1,%2,%3};"
        : "+f"(c[0]), "+f"(c[1]), "+f"(c[2]), "+f"(c[3])
        : "r"(a[0]), "r"(a[1]), "r"(a[2]), "r"(a[3]), "r"(b[0]), "r"(b[1]));
}

// map packed co slot -> gate-interleaved real co (gate = bits 3..4, ch = rest)
__device__ __forceinline__ int gmap_co(int p) {
    return ((p >> 3) & 3) * 64 + ((p & 7) | ((p >> 5) << 3));
}

// ---------------- weight pre-pack into m16n8k16 fragment order ----------------
__global__ void wprep(const float* __restrict__ wgt, int Cw, int Cin, int Cout,
                      int MTall, int nCh, int gmap, unsigned* __restrict__ whi,
                      unsigned* __restrict__ wlo)
{
    int idx = blockIdx.x * blockDim.x + threadIdx.x;
    int total = nCh * 9 * MTall * 128;
    if (idx >= total) return;
    int li = idx & 127;
    int j = li & 3, ln = li >> 2;
    int f = idx >> 7;
    int mtile = f % MTall;
    int tap = (f / MTall) % 9;
    int cb = f / (MTall * 9);
    int g = ln >> 2, q = ln & 3;
    int co = mtile * 16 + g + (j & 1) * 8;
    if (gmap) co = gmap_co(co);
    int kb = 2 * q + (j >> 1) * 8;
    int ci0 = cb * 16 + kb;
    float w0 = 0.f, w1 = 0.f;
    if (co < Cout) {
        if (ci0 < Cin)     w0 = wgt[((long)co * Cw + ci0) * 9 + tap];
        if (ci0 + 1 < Cin) w1 = wgt[((long)co * Cw + ci0 + 1) * 9 + tap];
    }
    __nv_bfloat16 h0, l0, h1, l1;
    splitbf(w0, h0, l0);
    splitbf(w1, h1, l1);
    whi[idx] = packbf(h0, h1);
    wlo[idx] = packbf(l0, l1);
}

// =============== implicit-GEMM 3x3 conv, bf16 hi/lo split, m16n8k16 ===============
// SPLIT=3: hi/lo split (~fp32); SPLIT=1: plain bf16. Split phases outermost.
// Optional aux channel: exact fp32 conv in epilogue.
// Optional FUSED ConvLSTM epilogue (MBLK=64 + gate-interleaved weights): each
// thread holds all 4 gates of one channel -> computes h/c directly, z never
// touches memory.
template <int MBLK, int WN, int SPLIT>
__global__ void __launch_bounds__(256, 2) mmaconv(
    const float* __restrict__ in0, int n0, long c0s, long b0s, long r0s,
    const float* __restrict__ in1, int n1, long c1s, long b1s, long r1s,
    const float* __restrict__ in2, int n2, long c2s, long b2s, long r2s,
    const unsigned* __restrict__ whi, const unsigned* __restrict__ wlo, int MTall,
    const float* __restrict__ aux, long aux_bs,
    const float* __restrict__ wax, int wstr,
    const float* __restrict__ bias, int act,
    float* __restrict__ out, long o_rs, long obs, int Cin, int Cout,
    const float* __restrict__ fcin, long fcin_bs,
    float* __restrict__ fh, long fh_bs,
    float* __restrict__ fc, long fc_bs)
{
    constexpr int WM = 8 / WN;
    constexpr int MT = MBLK / (16 * WM);
    constexpr int NT = 32 / WN;

    __shared__ unsigned in_hi[2][8 * 360];
    __shared__ unsigned in_lo[(SPLIT == 3) ? 2 : 1][(SPLIT == 3) ? 8 * 360 : 1];
    __shared__ float auxs[18 * 19];

    int b = blockIdx.z % Bn;
    int r = blockIdx.z / Bn;
    int cobase = blockIdx.y * MBLK;
    int ty0 = (blockIdx.x >> 3) * 16, tx0 = (blockIdx.x & 7) * 16;

    int tid = threadIdx.x;
    int wid = tid >> 5, lane = tid & 31;
    int g = lane >> 2, q = lane & 3;
    int cowb = (wid / WN) * (MT * 16);
    int pwb  = (wid % WN) * (NT * 8);

    int pixoff[NT];
#pragma unroll
    for (int nt = 0; nt < NT; nt++) {
        int px = pwb + nt * 8 + g;
        pixoff[nt] = (px >> 4) * 19 + (px & 15);
    }

    float acc[MT][NT][4];
#pragma unroll
    for (int mt = 0; mt < MT; mt++)
#pragma unroll
        for (int nt = 0; nt < NT; nt++)
#pragma unroll
            for (int i = 0; i < 4; i++) acc[mt][nt][i] = 0.f;

    if (aux) {
        for (int i = tid; i < 324; i += 256) {
            int rr = i / 18, cc = i - rr * 18;
            int gy = ty0 + rr - 1, gx = tx0 + cc - 1;
            float v = 0.f;
            if (gy >= 0 && gy < Hdim && gx >= 0 && gx < Wdim)
                v = aux[(long)b * aux_bs + gy * Wdim + gx];
            auxs[rr * 19 + cc] = v;
        }
    }

    auto ldci = [&](int cig, int go) -> float {
        if (cig >= Cin) return 0.f;
        const float* src;
        if (cig < n0)           src = in0 + (long)b * b0s + (long)r * r0s + (long)cig * c0s;
        else if (cig < n0 + n1) src = in1 + (long)b * b1s + (long)r * r1s + (long)(cig - n0) * c1s;
        else                    src = in2 + (long)b * b2s + (long)r * r2s + (long)(cig - n0 - n1) * c2s;
        return src[go];
    };
    auto stage = [&](int cb, int buf) {
#pragma unroll
        for (int jj = 0; jj < 11; jj++) {
            int i = tid + jj * 256;
            if (i >= 2592) continue;
            int cp = i / 324; int rem = i - cp * 324;
            int rr = rem / 18, cc = rem - rr * 18;
            int gy = ty0 + rr - 1, gx = tx0 + cc - 1;
            float v0 = 0.f, v1 = 0.f;
            if (gy >= 0 && gy < Hdim && gx >= 0 && gx < Wdim) {
                int go = gy * Wdim + gx;
                int ci0 = cb * 16 + 2 * cp;
                v0 = ldci(ci0, go);
                v1 = ldci(ci0 + 1, go);
            }
            __nv_bfloat16 h0, l0, h1, l1;
            splitbf(v0, h0, l0);
            splitbf(v1, h1, l1);
            int so = cp * 360 + rr * 19 + cc;
            in_hi[buf][so] = packbf(h0, h1);
            if (SPLIT == 3) in_lo[buf][so] = packbf(l0, l1);
        }
    };

    int nCh = (Cin + 15) >> 4;
    stage(0, 0);
    __syncthreads();

    for (int cb = 0; cb < nCh; cb++) {
        int buf = cb & 1;
        if (cb + 1 < nCh) stage(cb + 1, buf ^ 1);

        long wchunk = (long)cb * 9 * MTall * 128;
#pragma unroll
        for (int tap = 0; tap < 9; tap++) {
            int toff = (tap / 3) * 19 + (tap % 3);
            const unsigned* bh0 = &in_hi[buf][q * 360 + toff];
            const unsigned* bh1 = &in_hi[buf][(q + 4) * 360 + toff];
            const unsigned* bl0 = &in_lo[(SPLIT == 3) ? buf : 0][(SPLIT == 3) ? q * 360 + toff : 0];
            const unsigned* bl1 = &in_lo[(SPLIT == 3) ? buf : 0][(SPLIT == 3) ? (q + 4) * 360 + toff : 0];
#pragma unroll
            for (int ph = 0; ph < SPLIT; ph++) {
                uint4 afr[MT];
#pragma unroll
                for (int mt = 0; mt < MT; mt++) {
                    int mtg = (cobase >> 4) + (cowb >> 4) + mt;
                    long fb = wchunk + ((long)tap * MTall + mtg) * 128 + lane * 4;
                    afr[mt] = (ph == 2) ? *(const uint4*)&wlo[fb]
                                        : *(const uint4*)&whi[fb];
                }
#pragma unroll
                for (int nt = 0; nt < NT; nt++) {
                    unsigned bb[2];
                    if (ph == 1) { bb[0] = bl0[pixoff[nt]]; bb[1] = bl1[pixoff[nt]]; }
                    else         { bb[0] = bh0[pixoff[nt]]; bb[1] = bh1[pixoff[nt]]; }
#pragma unroll
                    for (int mt = 0; mt < MT; mt++)
                        mma16(acc[mt][nt], (const unsigned*)&afr[mt], bb);
                }
            }
        }
        __syncthreads();
    }

    // ---- FUSED ConvLSTM epilogue (gate-interleaved packing, MT==2 only) ----
    if (MT == 2 && fh != nullptr) {
        int S = cobase + cowb + g;                        // packed slot of gate i
        int chg = (S & 7) | ((S >> 5) << 3);              // logical channel 0..63
#pragma unroll
        for (int nt = 0; nt < NT; nt++) {
            int px = pwb + nt * 8 + 2 * q;
            int pr = px >> 4, pc = px & 15;
            int gp = (ty0 + pr) * Wdim + tx0 + pc;
            float zv[4][2];
#pragma unroll
            for (int gt = 0; gt < 4; gt++) {
                int co = gt * 64 + chg;
                float bs = bias[co];
                float v0 = acc[gt >> 1][nt][(gt & 1) * 2] + bs;
                float v1 = acc[gt >> 1][nt][(gt & 1) * 2 + 1] + bs;
                if (aux) {
#pragma unroll
                    for (int dy = 0; dy < 3; dy++)
#pragma unroll
                        for (int dx = 0; dx < 3; dx++) {
                            float w = wax[(long)co * wstr + dy * 3 + dx];
                            v0 = fmaf(w, auxs[(pr + dy) * 19 + pc + dx], v0);
                            v1 = fmaf(w, auxs[(pr + dy) * 19 + pc + 1 + dx], v1);
                        }
                }
                zv[gt][0] = v0; zv[gt][1] = v1;
            }
            long off = (long)chg * HWp + gp;
            float ci0 = fcin[(long)b * fcin_bs + off];
            float ci1 = fcin[(long)b * fcin_bs + off + 1];
            float c20 = sigm(zv[1][0]) * ci0 + sigm(zv[0][0]) * tanhf(zv[3][0]);
            float c21 = sigm(zv[1][1]) * ci1 + sigm(zv[0][1]) * tanhf(zv[3][1]);
            float h20 = sigm(zv[2][0]) * tanhf(c20);
            float h21 = sigm(zv[2][1]) * tanhf(c21);
            fh[(long)b * fh_bs + off] = h20;
            fh[(long)b * fh_bs + off + 1] = h21;
            fc[(long)b * fc_bs + off] = c20;
            fc[(long)b * fc_bs + off + 1] = c21;
        }
        return;
    }

    // ---- standard epilogue (+ exact fp32 aux-channel conv) ----
#pragma unroll
    for (int mt = 0; mt < MT; mt++) {
#pragma unroll
        for (int half = 0; half < 2; half++) {
            int co = cobase + cowb + mt * 16 + g + half * 8;
            if (co >= Cout) continue;
            float bs = bias ? bias[co] : 0.f;
            float w9[9];
            if (aux) {
#pragma unroll
                for (int t9 = 0; t9 < 9; t9++) w9[t9] = wax[(long)co * wstr + t9];
            }
            float* op = out + (long)r * o_rs + (long)b * obs + (long)co * HWp;
#pragma unroll
            for (int nt = 0; nt < NT; nt++) {
                int px = pwb + nt * 8 + 2 * q;
                int pr = px >> 4, pc = px & 15;
                int gp = (ty0 + pr) * Wdim + tx0 + pc;
                float v0 = acc[mt][nt][half * 2] + bs;
                float v1 = acc[mt][nt][half * 2 + 1] + bs;
                if (aux) {
#pragma unroll
                    for (int dy = 0; dy < 3; dy++)
#pragma unroll
                        for (int dx = 0; dx < 3; dx++) {
                            float w = w9[dy * 3 + dx];
                            v0 = fmaf(w, auxs[(pr + dy) * 19 + pc + dx], v0);
                            v1 = fmaf(w, auxs[(pr + dy) * 19 + pc + 1 + dx], v1);
                        }
                }
                if (act) { v0 = tanhf(v0); v1 = tanhf(v1); }
                op[gp] = v0; op[gp + 1] = v1;
            }
        }
    }
}

// =============== FFMA fallback conv (small Cout paths) ===============
template <int CB, int ACT>
__global__ void __launch_bounds__(256) convk(
    const float* __restrict__ in0, int n0, long c0s, long b0s, long r0s,
    const float* __restrict__ in1, int n1, long c1s, long b1s, long r1s,
    const float* __restrict__ in2, int n2, long c2s, long b2s, long r2s,
    const float* __restrict__ wgt, int Cw,
    const float* __restrict__ bias,
    const float* __restrict__ radd, long radd_rs, long radd_bs, int ring_s,
    float* __restrict__ out, long o_rs, long obs,
    int Cin, int Cout, int nCo)
{
    __shared__ float tile[2][34 * 34];
    __shared__ float wsm[2][CB][9];

    int z = blockIdx.z;
    int cb = z % nCo;
    int zb = z / nCo;
    int b = zb % Bn;
    int r = zb / Bn;
    int cobase = cb * CB;

    int tid = threadIdx.x;
    int txc = tid & 15, tyr = tid >> 4;
    int x0 = blockIdx.x * 32, y0 = blockIdx.y * 32;

    int goff[5]; bool gok[5];
#pragma unroll
    for (int j = 0; j < 5; j++) {
        int i = tid + j * 256;
        int rr = i / 34, cc = i - rr * 34;
        int gy = y0 + rr - 1, gx = x0 + cc - 1;
        gok[j] = (i < 34 * 34) && (gy >= 0) && (gy < Hdim) && (gx >= 0) && (gx < Wdim);
        goff[j] = gy * Wdim + gx;
    }
    bool wldr = tid < CB * 9;
    int wco = tid / 9, wk = tid - wco * 9;
    bool wok = wldr && (cobase + wco < Cout);
    long wbase = ((long)(cobase + wco) * Cw) * 9 + wk;

    float acc[CB][4];
#pragma unroll
    for (int co = 0; co < CB; co++)
#pragma unroll
        for (int qq = 0; qq < 4; qq++) acc[co][qq] = 0.f;

    auto load_cin = [&](int cin, int p) {
        const float* src;
        if (cin < n0)           src = in0 + (long)b * b0s + (long)r * r0s + (long)cin * c0s;
        else if (cin < n0 + n1) src = in1 + (long)b * b1s + (long)r * r1s + (long)(cin - n0) * c1s;
        else                    src = in2 + (long)b * b2s + (long)r * r2s + (long)(cin - n0 - n1) * c2s;
#pragma unroll
        for (int j = 0; j < 4; j++)
            tile[p][tid + j * 256] = gok[j] ? src[goff[j]] : 0.f;
        if (tid + 1024 < 34 * 34)
            tile[p][tid + 1024] = gok[4] ? src[goff[4]] : 0.f;
        if (wldr)
            wsm[p][wco][wk] = wok ? wgt[wbase + (long)cin * 9] : 0.f;
    };

    load_cin(0, 0);
    __syncthreads();

    for (int cin = 0; cin < Cin; cin++) {
        int p = cin & 1;
        if (cin + 1 < Cin) load_cin(cin + 1, p ^ 1);

        float v[4][4];
#pragma unroll
        for (int rr = 0; rr < 4; rr++)
#pragma unroll
            for (int cc = 0; cc < 4; cc++)
                v[rr][cc] = tile[p][(2 * tyr + rr) * 34 + 2 * txc + cc];

#pragma unroll
        for (int co = 0; co < CB; co++) {
#pragma unroll
            for (int k = 0; k < 9; k++) {
                float w = wsm[p][co][k];
                int dy = k / 3, dx = k % 3;
                acc[co][0] = fmaf(v[dy][dx],         w, acc[co][0]);
                acc[co][1] = fmaf(v[dy][dx + 1],     w, acc[co][1]);
                acc[co][2] = fmaf(v[dy + 1][dx],     w, acc[co][2]);
                acc[co][3] = fmaf(v[dy + 1][dx + 1], w, acc[co][3]);
            }
        }
        __syncthreads();
    }

    int ox = x0 + 2 * txc, oy = y0 + 2 * tyr;
    long p0 = (long)oy * Wdim + ox;
    int pr = (radd && ring_s >= 0) ? (ring_s + r) % Tn : r;
#pragma unroll
    for (int co = 0; co < CB; co++) {
        int c = cobase + co;
        if (c >= Cout) continue;
        float bs = bias ? bias[c] : 0.f;
        float v0 = acc[co][0] + bs, v1 = acc[co][1] + bs;
        float v2 = acc[co][2] + bs, v3 = acc[co][3] + bs;
        if (radd) {
            const float* ra = radd + (long)pr * radd_rs + (long)b * radd_bs + (long)c * HWp + p0;
            v0 += ra[0]; v1 += ra[1]; v2 += ra[Wdim]; v3 += ra[Wdim + 1];
        }
        if (ACT == 1) { v0 = tanhf(v0); v1 = tanhf(v1); v2 = tanhf(v2); v3 = tanhf(v3); }
        float* o = out + (long)r * o_rs + (long)b * obs + (long)c * HWp + p0;
        o[0] = v0; o[1] = v1; o[Wdim] = v2; o[Wdim + 1] = v3;
    }
}

// ---------------- LSTM pointwise gate update (small convs only) ----------------
__global__ void lstm_k(const float* __restrict__ z, const float* __restrict__ cin, long cin_bs,
                       float* __restrict__ hout, long h_bs, float* __restrict__ cout_, long c_bs,
                       float* __restrict__ hout2, long h2_bs, int C)
{
    long total = (long)Bn * C * HWp;
    long idx = (long)blockIdx.x * blockDim.x + threadIdx.x;
    if (idx >= total) return;
    long CHW = (long)C * HWp;
    int b = (int)(idx / CHW);
    long r = idx - (long)b * CHW;
    const float* zb = z + (long)b * 4 * CHW;
    float zi = zb[r], zf = zb[CHW + r], zo = zb[2 * CHW + r], zg = zb[3 * CHW + r];
    float c = cin[(long)b * cin_bs + r];
    float c2 = sigm(zf) * c + sigm(zi) * tanhf(zg);
    float h2 = sigm(zo) * tanhf(c2);
    hout[(long)b * h_bs + r] = h2;
    cout_[(long)b * c_bs + r] = c2;
    if (hout2) hout2[(long)b * h2_bs + r] = h2;
}

// ---------------- input attention softmax + compounding reweight ----------------
__global__ void inattn_k(const float* __restrict__ score, float* __restrict__ xx)
{
    int idx = blockIdx.x * blockDim.x + threadIdx.x;
    if (idx >= Bn * HWp) return;
    int b = idx / HWp, p = idx - b * HWp;
    const float* sc = score + (long)b * Dn * HWp + p;
    float s[Dn];
    float m = -1e30f;
#pragma unroll
    for (int k = 0; k < Dn; k++) { s[k] = sc[(long)k * HWp]; m = fmaxf(m, s[k]); }
    float sum = 0.f;
#pragma unroll
    for (int k = 0; k < Dn; k++) { s[k] = __expf(s[k] - m); sum += s[k]; }
    float inv = 1.f / sum;
    float* xb = xx + (long)b * Tn * Dn * HWp + p;
#pragma unroll
    for (int k = 0; k < Dn; k++) {
        float a = s[k] * inv;
        for (int t = 0; t < Tn; t++) xb[((long)t * Dn + k) * HWp] *= a;
    }
}

// ---------------- temporal attention softmax + weighted sum ----------------
__global__ void tattn_k(const float* __restrict__ score, const float* __restrict__ hs1,
                        float* __restrict__ hatt, int s)
{
    int idx = blockIdx.x * blockDim.x + threadIdx.x;
    if (idx >= Bn * HWp) return;
    int b = idx / HWp, p = idx - b * HWp;
    const float* sc = score + (long)b * Tn * HWp + p;
    float bt[Tn];
    float m = -1e30f;
#pragma unroll
    for (int t = 0; t < Tn; t++) { bt[t] = sc[(long)t * HWp]; m = fmaxf(m, bt[t]); }
    float sum = 0.f;
#pragma unroll
    for (int t = 0; t < Tn; t++) { bt[t] = __expf(bt[t] - m); sum += bt[t]; }
    float inv = 1.f / sum;
    float acc[64];
#pragma unroll
    for (int c = 0; c < 64; c++) acc[c] = 0.f;
    for (int t = 0; t < Tn; t++) {
        int phys = (s + t) % Tn;
        const float* hb = hs1 + ((long)b * Tn + phys) * 64 * HWp + p;
        float w = bt[t] * inv;
#pragma unroll
        for (int c = 0; c < 64; c++) acc[c] = fmaf(hb[(long)c * HWp], w, acc[c]);
    }
    float* ob = hatt + (long)b * 64 * HWp + p;
#pragma unroll
    for (int c = 0; c < 64; c++) ob[(long)c * HWp] = acc[c];
}

// ---------------- host side ----------------
struct Seg { const float* p; int n; long cs, bs, rs; };
static inline Seg mkseg(const float* p, int n, long cs, long bs, long rs) {
    Seg s; s.p = p; s.n = n; s.cs = cs; s.bs = bs; s.rs = rs; return s;
}

static void conv(int CB, int ACT, Seg a, Seg b, Seg c,
                 const float* w, int Cw, const float* bias,
                 const float* radd, long rrs, long rbs, int ring_s,
                 float* out, long ors, long obs, int Cin, int Cout, int R)
{
    int nCo = (Cout + CB - 1) / CB;
    dim3 grid(Wdim / 32, Hdim / 32, R * Bn * nCo);
#define CARGS a.p, a.n, a.cs, a.bs, a.rs, b.p, b.n, b.cs, b.bs, b.rs, c.p, c.n, c.cs, c.bs, c.rs, \
              w, Cw, bias, radd, rrs, rbs, ring_s, out, ors, obs, Cin, Cout, nCo
    if (CB == 8 && ACT == 1) convk<8, 1><<<grid, 256>>>(CARGS);
    else if (CB == 8)        convk<8, 0><<<grid, 256>>>(CARGS);
    else                     convk<1, 0><<<grid, 256>>>(CARGS);
#undef CARGS
}

static void mconv(int MBLK, int SPLIT, Seg a, Seg b, Seg c,
                  const unsigned* whi, const unsigned* wlo, int MTall,
                  const float* aux, long aux_bs, const float* wax, int wstr,
                  const float* bias, int act,
                  float* out, long ors, long obs, int Cin, int Cout, int R,
                  const float* fcin = nullptr, long fcin_bs = 0,
                  float* fh = nullptr, long fh_bs = 0,
                  float* fc = nullptr, long fc_bs = 0)
{
    dim3 grid(64, (Cout + MBLK - 1) / MBLK, R * Bn);
#define MARGS a.p, a.n, a.cs, a.bs, a.rs, b.p, b.n, b.cs, b.bs, b.rs, c.p, c.n, c.cs, c.bs, c.rs, \
              whi, wlo, MTall, aux, aux_bs, wax, wstr, bias, act, out, ors, obs, Cin, Cout, \
              fcin, fcin_bs, fh, fh_bs, fc, fc_bs
    if (MBLK == 64)                     mmaconv<64, 4, 3><<<grid, 256>>>(MARGS);
    else if (MBLK == 32 && SPLIT == 1)  mmaconv<32, 8, 1><<<grid, 256>>>(MARGS);
    else if (MBLK == 32)                mmaconv<32, 8, 3><<<grid, 256>>>(MARGS);
    else                                mmaconv<16, 8, 3><<<grid, 256>>>(MARGS);
#undef MARGS
}

extern "C" void kernel_launch(void* const* d_in, const int* in_sizes, int n_in,
                              void* d_out, int out_size)
{
    const float* x      = (const float*)d_in[0];
    const float* h0     = (const float*)d_in[1];
    const float* c0     = (const float*)d_in[2];
    const float* h1     = (const float*)d_in[3];
    const float* c1     = (const float*)d_in[4];
    const float* w_enc0 = (const float*)d_in[5];
    const float* b_enc0 = (const float*)d_in[6];
    const float* w_enc1 = (const float*)d_in[7];
    const float* b_enc1 = (const float*)d_in[8];
    const float* w_dec0 = (const float*)d_in[9];
    const float* b_dec0 = (const float*)d_in[10];
    const float* w_dec1 = (const float*)d_in[11];
    const float* b_dec1 = (const float*)d_in[12];
    const float* wa1    = (const float*)d_in[13];
    const float* ba1    = (const float*)d_in[14];
    const float* wa2    = (const float*)d_in[15];
    const float* ba2    = (const float*)d_in[16];
    const float* wt1    = (const float*)d_in[17];
    const float* bt1    = (const float*)d_in[18];
    const float* wt2    = (const float*)d_in[19];
    const float* bt2    = (const float*)d_in[20];

    float *xx, *hs0, *cs0, *hs1, *cs1, *score, *hid, *z, *hatt, *tc;
    unsigned *whi, *wlo;
    cudaGetSymbolAddress((void**)&xx, g_xx);
    cudaGetSymbolAddress((void**)&hs0, g_hs0);
    cudaGetSymbolAddress((void**)&cs0, g_cs0);
    cudaGetSymbolAddress((void**)&hs1, g_hs1);
    cudaGetSymbolAddress((void**)&cs1, g_cs1);
    cudaGetSymbolAddress((void**)&score, g_score);
    cudaGetSymbolAddress((void**)&hid, g_hid);
    cudaGetSymbolAddress((void**)&z, g_z);
    cudaGetSymbolAddress((void**)&hatt, g_hatt);
    cudaGetSymbolAddress((void**)&tc, g_tc);
    cudaGetSymbolAddress((void**)&whi, g_whi);
    cudaGetSymbolAddress((void**)&wlo, g_wlo);

    cudaMemcpyAsync(xx, x, sizeof(float) * (size_t)Bn * Tn * Dn * HWp,
                    cudaMemcpyDeviceToDevice);

    // ---- pre-pack mma weights (enc1/dec0 gate-interleaved for fused LSTM) ----
    const int PT = 256;
    wprep<<<(SZ_ENC1  + PT - 1) / PT, PT>>>(w_enc1 + 9, 65, 64, 256, 16, 4, 1, whi + OFF_ENC1,  wlo + OFF_ENC1);
    wprep<<<(SZ_DEC0  + PT - 1) / PT, PT>>>(w_dec0 + 9, 65, 64, 256, 16, 4, 1, whi + OFF_DEC0,  wlo + OFF_DEC0);
    wprep<<<(SZ_WA1   + PT - 1) / PT, PT>>>(wa1,        12, 12, 32,  2, 1, 0,  whi + OFF_WA1,   wlo + OFF_WA1);
    wprep<<<(SZ_WT1HC + PT - 1) / PT, PT>>>(wt1 + 9,   129, 128, 32, 2, 8, 0,  whi + OFF_WT1HC, wlo + OFF_WT1HC);
    wprep<<<(SZ_ENC0  + PT - 1) / PT, PT>>>(w_enc0,     11, 11, 4,   1, 1, 0,  whi + OFF_ENC0,  wlo + OFF_ENC0);
    wprep<<<(SZ_DEC1  + PT - 1) / PT, PT>>>(w_dec1,     65, 64, 4,   1, 4, 0,  whi + OFF_DEC1,  wlo + OFF_DEC1);

    Seg none = mkseg(nullptr, 0, 0, 0, 0);
    const int thr = 256;
    const long HID_RS = (long)Bn * 32 * HWp;

    // ======== encoder layer 0 (hidden 1), compounding input attention ========
    for (int t = 0; t < Tn; t++) {
        const float* hp = (t == 0) ? h0 : hs0 + (long)(t - 1) * HWp;
        long hbs        = (t == 0) ? (long)HWp : (long)Tn * HWp;
        const float* cp = (t == 0) ? c0 : cs0 + (long)(t - 1) * HWp;
        long cbs = hbs;

        mconv(32, 3,
              mkseg(xx, Tn, (long)Dn * HWp, (long)Tn * Dn * HWp, (long)HWp),
              mkseg(hp, 1, 0, hbs, 0),
              mkseg(cp, 1, 0, cbs, 0),
              whi + OFF_WA1, wlo + OFF_WA1, 2, nullptr, 0, nullptr, 0, ba1, 1,
              hid, HID_RS, 32L * HWp, 12, 32, Dn);
        conv(1, 0,
             mkseg(hid, 32, HWp, 32L * HWp, HID_RS), none, none,
             wa2, 32, ba2, nullptr, 0, 0, -1,
             score, (long)HWp, (long)Dn * HWp, 32, 1, Dn);
        inattn_k<<<(Bn * HWp + thr - 1) / thr, thr>>>(score, xx);

        mconv(16, 3,
              mkseg(xx + (long)t * Dn * HWp, Dn, (long)HWp, (long)Tn * Dn * HWp, 0),
              mkseg(hp, 1, 0, hbs, 0), none,
              whi + OFF_ENC0, wlo + OFF_ENC0, 1, nullptr, 0, nullptr, 0, b_enc0, 0,
              z, 0, 4L * HWp, 11, 4, 1);
        long n = (long)Bn * HWp;
        lstm_k<<<(n + thr - 1) / thr, thr>>>(z, cp, cbs,
                                             hs0 + (long)t * HWp, (long)Tn * HWp,
                                             cs0 + (long)t * HWp, (long)Tn * HWp,
                                             nullptr, 0, 1);
    }

    // ======== encoder layer 1 (65->256): fused conv+LSTM ========
    for (int t = 0; t < Tn; t++) {
        const float* hp = (t == 0) ? h1 : hs1 + (long)(t - 1) * 64 * HWp;
        long hbs        = (t == 0) ? 64L * HWp : (long)Tn * 64 * HWp;
        const float* cp = (t == 0) ? c1 : cs1 + (long)(t - 1) * 64 * HWp;

        mconv(64, 3,
              mkseg(hp, 64, HWp, hbs, 0), none, none,
              whi + OFF_ENC1, wlo + OFF_ENC1, 16,
              hs0 + (long)t * HWp, (long)Tn * HWp, w_enc1, 585,
              b_enc1, 0,
              z, 0, 256L * HWp, 64, 256, 1,
              cp, hbs,
              hs1 + (long)t * 64 * HWp, (long)Tn * 64 * HWp,
              cs1 + (long)t * 64 * HWp, (long)Tn * 64 * HWp);
    }

    // ======== temporal-attn h/c conv cache (128->32) all slots: 1-split ========
    mconv(32, 1,
          mkseg(hs1, 64, HWp, (long)Tn * 64 * HWp, 64L * HWp),
          mkseg(cs1, 64, HWp, (long)Tn * 64 * HWp, 64L * HWp), none,
          whi + OFF_WT1HC, wlo + OFF_WT1HC, 2, nullptr, 0, nullptr, 0, bt1, 0,
          tc, HID_RS, 32L * HWp, 128, 32, Tn);

    // ======== decoder ========
    float* out = (float*)d_out;
    for (int s = 0; s < 5; s++) {
        const float* yp; long ybs;
        if (s == 0) { yp = x + 90L * HWp; ybs = 100L * HWp; }
        else        { yp = hs0 + (long)(s - 1) * HWp; ybs = (long)Tn * HWp; }

        conv(8, 1,
             mkseg(yp, 1, 0, ybs, 0), none, none,
             wt1, 129, nullptr, tc, HID_RS, 32L * HWp, s,
             hid, HID_RS, 32L * HWp, 1, 32, Tn);
        conv(1, 0,
             mkseg(hid, 32, HWp, 32L * HWp, HID_RS), none, none,
             wt2, 32, bt2, nullptr, 0, 0, -1,
             score, (long)HWp, (long)Tn * HWp, 32, 1, Tn);
        tattn_k<<<(Bn * HWp + thr - 1) / thr, thr>>>(score, hs1, hatt, s);

        int pl = (s + 9) % Tn;

        // dec0 (65->256): fused conv+LSTM
        mconv(64, 3,
              mkseg(hatt, 64, HWp, 64L * HWp, 0), none, none,
              whi + OFF_DEC0, wlo + OFF_DEC0, 16,
              yp, ybs, w_dec0, 585,
              b_dec0, 0,
              z, 0, 256L * HWp, 64, 256, 1,
              cs1 + (long)pl * 64 * HWp, (long)Tn * 64 * HWp,
              hs1 + (long)s * 64 * HWp, (long)Tn * 64 * HWp,
              cs1 + (long)s * 64 * HWp, (long)Tn * 64 * HWp);

        // refresh tc cache for slot s: 1-split
        mconv(32, 1,
              mkseg(hs1 + (long)s * 64 * HWp, 64, HWp, (long)Tn * 64 * HWp, 0),
              mkseg(cs1 + (long)s * 64 * HWp, 64, HWp, (long)Tn * 64 * HWp, 0), none,
              whi + OFF_WT1HC, wlo + OFF_WT1HC, 2, nullptr, 0, nullptr, 0, bt1, 0,
              tc + (long)s * HID_RS, 0, 32L * HWp, 128, 32, 1);

        // dec1 (65->4): MMA over 64 hs1-ch + exact fp32 aux ch (hs0 last)
        mconv(16, 3,
              mkseg(hs1 + (long)s * 64 * HWp, 64, HWp, (long)Tn * 64 * HWp, 0), none, none,
              whi + OFF_DEC1, wlo + OFF_DEC1, 1,
              hs0 + (long)pl * HWp, (long)Tn * HWp, w_dec1 + 64 * 9, 585,
              b_dec1, 0,
              z, 0, 4L * HWp, 64, 4, 1);
        long n1 = (long)Bn * HWp;
        lstm_k<<<(n1 + thr - 1) / thr, thr>>>(z, cs0 + (long)pl * HWp, (long)Tn * HWp,
                                              hs0 + (long)s * HWp, (long)Tn * HWp,
                                              cs0 + (long)s * HWp, (long)Tn * HWp,
                                              out + (long)s * HWp, 5L * HWp, 1);
    }
}